// round 1
// baseline (speedup 1.0000x reference)
#include <cuda_runtime.h>
#include <cstdint>

#define SEQ  2048
#define HID  3072
#define NH   24
#define HD   128
#define CAD  4096
#define IPT  128

// Scratch (static __device__ — no allocation allowed)
__device__ float g_Q[SEQ * HID];
__device__ float g_K[SEQ * HID];
__device__ float g_V[SEQ * HID];
__device__ float g_IPK[IPT * HID];
__device__ float g_IPV[IPT * HID];

// ---------------------------------------------------------------------------
// SGEMM (NT): C[M,N] = A[M,K] @ B[N,K]^T (+ bias). BM=BN=64, BK=16, 256 thr,
// 4x4 per-thread microtile. M,N multiples of 64; K multiple of 16 (true here).
// ---------------------------------------------------------------------------
__global__ __launch_bounds__(256) void sgemm_nt(
    const float* __restrict__ A, const float* __restrict__ B,
    const float* __restrict__ bias, int outSel, int M, int N, int K)
{
    __shared__ float As[16][68];
    __shared__ float Bs[16][68];

    float* C = (outSel == 0) ? g_Q : (outSel == 1) ? g_K :
               (outSel == 2) ? g_V : (outSel == 3) ? g_IPK : g_IPV;

    const int tid = threadIdx.x;
    const int tx = tid & 15;
    const int ty = tid >> 4;
    const int m0 = blockIdx.y * 64;
    const int n0 = blockIdx.x * 64;
    const int lr = tid >> 2;     // 0..63
    const int lc = tid & 3;      // 0..3

    float acc[4][4];
#pragma unroll
    for (int i = 0; i < 4; i++)
#pragma unroll
        for (int j = 0; j < 4; j++) acc[i][j] = 0.f;

    const float* Arow = A + (size_t)(m0 + lr) * K + lc * 4;
    const float* Brow = B + (size_t)(n0 + lr) * K + lc * 4;

    for (int k0 = 0; k0 < K; k0 += 16) {
        float4 av = *(const float4*)(Arow + k0);
        float4 bv = *(const float4*)(Brow + k0);
        As[lc * 4 + 0][lr] = av.x; As[lc * 4 + 1][lr] = av.y;
        As[lc * 4 + 2][lr] = av.z; As[lc * 4 + 3][lr] = av.w;
        Bs[lc * 4 + 0][lr] = bv.x; Bs[lc * 4 + 1][lr] = bv.y;
        Bs[lc * 4 + 2][lr] = bv.z; Bs[lc * 4 + 3][lr] = bv.w;
        __syncthreads();

#pragma unroll
        for (int kk = 0; kk < 16; kk++) {
            float4 a4 = *(const float4*)&As[kk][ty * 4];
            float4 b4 = *(const float4*)&Bs[kk][tx * 4];
            float af[4] = {a4.x, a4.y, a4.z, a4.w};
            float bf[4] = {b4.x, b4.y, b4.z, b4.w};
#pragma unroll
            for (int i = 0; i < 4; i++)
#pragma unroll
                for (int j = 0; j < 4; j++)
                    acc[i][j] += af[i] * bf[j];
        }
        __syncthreads();
    }

#pragma unroll
    for (int i = 0; i < 4; i++) {
        int row = m0 + ty * 4 + i;
#pragma unroll
        for (int j = 0; j < 4; j++) {
            int col = n0 + tx * 4 + j;
            float b = bias ? bias[col] : 0.f;
            C[(size_t)row * N + col] = acc[i][j] + b;
        }
    }
}

// ---------------------------------------------------------------------------
// RMSNorm(w, eps=1e-6) + interleaved RoPE on g_Q / g_K, in place.
// One warp per (s,h) row of 128; 8 warps per block. blockIdx.y: 0=Q, 1=K.
// ---------------------------------------------------------------------------
__global__ __launch_bounds__(256) void rms_rope(
    const float* __restrict__ cosp, const float* __restrict__ sinp,
    const float* __restrict__ qw, const float* __restrict__ kw)
{
    const int warp = threadIdx.x >> 5;
    const int lane = threadIdx.x & 31;
    const int row = blockIdx.x * 8 + warp;           // 0 .. SEQ*NH-1
    float* X = (blockIdx.y == 0) ? g_Q : g_K;
    const float* w = (blockIdx.y == 0) ? qw : kw;
    const int s = row / NH;
    const size_t base = (size_t)row * HD + lane * 4;

    float4 x = *(const float4*)(X + base);
    float ss = x.x * x.x + x.y * x.y + x.z * x.z + x.w * x.w;
#pragma unroll
    for (int o = 16; o; o >>= 1) ss += __shfl_xor_sync(0xffffffffu, ss, o);
    float inv = rsqrtf(ss * (1.f / HD) + 1e-6f);

    float4 wv = *(const float4*)(w + lane * 4);
    float y0 = x.x * inv * wv.x, y1 = x.y * inv * wv.y;
    float y2 = x.z * inv * wv.z, y3 = x.w * inv * wv.w;

    float4 c  = *(const float4*)(cosp + (size_t)s * HD + lane * 4);
    float4 sn = *(const float4*)(sinp + (size_t)s * HD + lane * 4);
    float4 o;
    o.x = y0 * c.x - y1 * sn.x;
    o.y = y1 * c.y + y0 * sn.y;
    o.z = y2 * c.z - y3 * sn.z;
    o.w = y3 * c.w + y2 * sn.w;
    *(float4*)(X + base) = o;
}

// RMSNorm(eps=1e-5, no weight, no rope) on g_IPK / g_IPV in place.
__global__ __launch_bounds__(256) void ip_rms()
{
    const int warp = threadIdx.x >> 5;
    const int lane = threadIdx.x & 31;
    const int row = blockIdx.x * 8 + warp;           // 0 .. IPT*NH-1
    float* X = (blockIdx.y == 0) ? g_IPK : g_IPV;
    const size_t base = (size_t)row * HD + lane * 4;

    float4 x = *(const float4*)(X + base);
    float ss = x.x * x.x + x.y * x.y + x.z * x.z + x.w * x.w;
#pragma unroll
    for (int o = 16; o; o >>= 1) ss += __shfl_xor_sync(0xffffffffu, ss, o);
    float inv = rsqrtf(ss * (1.f / HD) + 1e-5f);
    x.x *= inv; x.y *= inv; x.z *= inv; x.w *= inv;
    *(float4*)(X + base) = x;
}

// ---------------------------------------------------------------------------
// Fused flash attention (fp32): for each (head, 32-query tile) block,
// phase 0 = main attention over S=2048 keys, phase 1 = IP attention over
// T=128 keys. out = O_main + O_ip. 128 threads; thread owns output column tid.
// ---------------------------------------------------------------------------
__global__ __launch_bounds__(128) void attn_kernel(float* __restrict__ out)
{
    __shared__ float qs[32][132];
    __shared__ float kv[32][132];
    __shared__ float sc[32][36];
    __shared__ float abuf[32];
    __shared__ float lbuf[32];

    const int tid = threadIdx.x;
    const int h = blockIdx.y;
    const int q0 = blockIdx.x * 32;
    const float scale = 0.08838834764831845f;  // 1/sqrt(128)

    // Load Q tile (pre-scaled)
#pragma unroll
    for (int it = 0; it < 8; it++) {
        int idx = it * 128 + tid;
        int r = idx >> 5, c4 = idx & 31;
        float4 v = *(const float4*)(g_Q + (size_t)(q0 + r) * HID + h * HD + c4 * 4);
        v.x *= scale; v.y *= scale; v.z *= scale; v.w *= scale;
        *(float4*)&qs[r][c4 * 4] = v;
    }

    float oacc[32];
#pragma unroll
    for (int i = 0; i < 32; i++) oacc[i] = 0.f;
    float mreg = -1e30f, lreg = 0.f;

    const int jg = tid & 3;     // score col group
    const int ir = tid >> 2;    // score row
    const int c = tid;          // output column
    __syncthreads();

    for (int phase = 0; phase < 2; phase++) {
        const float* Ksrc = phase ? g_IPK : g_K;
        const float* Vsrc = phase ? g_IPV : g_V;
        const int ntiles = phase ? (IPT / 32) : (SEQ / 32);

        for (int t = 0; t < ntiles; t++) {
            const int k0 = t * 32;

            // K tile
#pragma unroll
            for (int it = 0; it < 8; it++) {
                int idx = it * 128 + tid;
                int r = idx >> 5, c4 = idx & 31;
                *(float4*)&kv[r][c4 * 4] =
                    *(const float4*)(Ksrc + (size_t)(k0 + r) * HID + h * HD + c4 * 4);
            }
            __syncthreads();

            // S = q.kT
            float a8[8];
#pragma unroll
            for (int jj = 0; jj < 8; jj++) a8[jj] = 0.f;
            for (int d4 = 0; d4 < HD; d4 += 4) {
                float4 q4 = *(const float4*)&qs[ir][d4];
#pragma unroll
                for (int jj = 0; jj < 8; jj++) {
                    float4 k4 = *(const float4*)&kv[jg * 8 + jj][d4];
                    a8[jj] += q4.x * k4.x + q4.y * k4.y + q4.z * k4.z + q4.w * k4.w;
                }
            }
#pragma unroll
            for (int jj = 0; jj < 8; jj++) sc[ir][jg * 8 + jj] = a8[jj];
            __syncthreads();

            // Online softmax (one thread per query row)
            if (tid < 32) {
                float tm = -1e30f;
#pragma unroll
                for (int j = 0; j < 32; j++) tm = fmaxf(tm, sc[tid][j]);
                float mnew = fmaxf(mreg, tm);
                float alpha = __expf(mreg - mnew);
                float ls = 0.f;
#pragma unroll
                for (int j = 0; j < 32; j++) {
                    float p = __expf(sc[tid][j] - mnew);
                    sc[tid][j] = p;
                    ls += p;
                }
                lreg = lreg * alpha + ls;
                mreg = mnew;
                abuf[tid] = alpha;
            }
            __syncthreads();

            // V tile (reuse kv)
#pragma unroll
            for (int it = 0; it < 8; it++) {
                int idx = it * 128 + tid;
                int r = idx >> 5, c4 = idx & 31;
                *(float4*)&kv[r][c4 * 4] =
                    *(const float4*)(Vsrc + (size_t)(k0 + r) * HID + h * HD + c4 * 4);
            }
            __syncthreads();

            // O += P @ V  (with rescale)
#pragma unroll
            for (int i = 0; i < 32; i++) oacc[i] *= abuf[i];
#pragma unroll
            for (int j4 = 0; j4 < 8; j4++) {
                float v0 = kv[j4 * 4 + 0][c];
                float v1 = kv[j4 * 4 + 1][c];
                float v2 = kv[j4 * 4 + 2][c];
                float v3 = kv[j4 * 4 + 3][c];
#pragma unroll
                for (int i = 0; i < 32; i++) {
                    float4 p4 = *(const float4*)&sc[i][j4 * 4];
                    oacc[i] += p4.x * v0 + p4.y * v1 + p4.z * v2 + p4.w * v3;
                }
            }
            __syncthreads();
        }

        // Finalize this phase
        if (tid < 32) lbuf[tid] = lreg;
        __syncthreads();
        if (phase == 0) {
#pragma unroll
            for (int i = 0; i < 32; i++)
                out[(size_t)(q0 + i) * HID + h * HD + c] = oacc[i] / lbuf[i];
#pragma unroll
            for (int i = 0; i < 32; i++) oacc[i] = 0.f;
            mreg = -1e30f; lreg = 0.f;
        } else {
#pragma unroll
            for (int i = 0; i < 32; i++)
                out[(size_t)(q0 + i) * HID + h * HD + c] += oacc[i] / lbuf[i];
        }
        __syncthreads();
    }
}

// ---------------------------------------------------------------------------
extern "C" void kernel_launch(void* const* d_in, const int* in_sizes, int n_in,
                              void* d_out, int out_size)
{
    const float* hidden = (const float*)d_in[0];
    const float* cosp   = (const float*)d_in[1];
    const float* sinp   = (const float*)d_in[2];
    const float* iph    = (const float*)d_in[3];
    const float* Wq     = (const float*)d_in[4];
    const float* bq     = (const float*)d_in[5];
    const float* Wk     = (const float*)d_in[6];
    const float* bk     = (const float*)d_in[7];
    const float* Wv     = (const float*)d_in[8];
    const float* bv     = (const float*)d_in[9];
    const float* nqw    = (const float*)d_in[10];
    const float* nkw    = (const float*)d_in[11];
    const float* Wkip   = (const float*)d_in[12];
    const float* Wvip   = (const float*)d_in[13];
    float* out = (float*)d_out;

    dim3 gProj(HID / 64, SEQ / 64);
    sgemm_nt<<<gProj, 256>>>(hidden, Wq, bq, 0, SEQ, HID, HID);
    sgemm_nt<<<gProj, 256>>>(hidden, Wk, bk, 1, SEQ, HID, HID);
    sgemm_nt<<<gProj, 256>>>(hidden, Wv, bv, 2, SEQ, HID, HID);

    dim3 gIp(HID / 64, IPT / 64);
    sgemm_nt<<<gIp, 256>>>(iph, Wkip, nullptr, 3, IPT, HID, CAD);
    sgemm_nt<<<gIp, 256>>>(iph, Wvip, nullptr, 4, IPT, HID, CAD);

    rms_rope<<<dim3(SEQ * NH / 8, 2), 256>>>(cosp, sinp, nqw, nkw);
    ip_rms<<<dim3(IPT * NH / 8, 2), 256>>>();

    attn_kernel<<<dim3(SEQ / 32, NH), 128>>>(out);
}

// round 2
// speedup vs baseline: 1.0022x; 1.0022x over previous
#include <cuda_runtime.h>
#include <cstdint>

#define SEQ  2048
#define HID  3072
#define NH   24
#define HD   128
#define CAD  4096
#define IPT  128

// Scratch (static __device__ — no allocation allowed)
__device__ float g_Q[SEQ * HID];
__device__ float g_K[SEQ * HID];
__device__ float g_V[SEQ * HID];
__device__ float g_IPK[IPT * HID];
__device__ float g_IPV[IPT * HID];

// ---------------------------------------------------------------------------
// SGEMM (NT): C[M,N] = A[M,K] @ B[N,K]^T (+ bias). BM=BN=64, BK=16, 256 thr,
// 4x4 per-thread microtile. M,N multiples of 64; K multiple of 16 (true here).
// ---------------------------------------------------------------------------
__global__ __launch_bounds__(256) void sgemm_nt(
    const float* __restrict__ A, const float* __restrict__ B,
    const float* __restrict__ bias, int outSel, int M, int N, int K)
{
    __shared__ float As[16][68];
    __shared__ float Bs[16][68];

    float* C = (outSel == 0) ? g_Q : (outSel == 1) ? g_K :
               (outSel == 2) ? g_V : (outSel == 3) ? g_IPK : g_IPV;

    const int tid = threadIdx.x;
    const int tx = tid & 15;
    const int ty = tid >> 4;
    const int m0 = blockIdx.y * 64;
    const int n0 = blockIdx.x * 64;
    const int lr = tid >> 2;     // 0..63
    const int lc = tid & 3;      // 0..3

    float acc[4][4];
#pragma unroll
    for (int i = 0; i < 4; i++)
#pragma unroll
        for (int j = 0; j < 4; j++) acc[i][j] = 0.f;

    const float* Arow = A + (size_t)(m0 + lr) * K + lc * 4;
    const float* Brow = B + (size_t)(n0 + lr) * K + lc * 4;

    for (int k0 = 0; k0 < K; k0 += 16) {
        float4 av = *(const float4*)(Arow + k0);
        float4 bv = *(const float4*)(Brow + k0);
        As[lc * 4 + 0][lr] = av.x; As[lc * 4 + 1][lr] = av.y;
        As[lc * 4 + 2][lr] = av.z; As[lc * 4 + 3][lr] = av.w;
        Bs[lc * 4 + 0][lr] = bv.x; Bs[lc * 4 + 1][lr] = bv.y;
        Bs[lc * 4 + 2][lr] = bv.z; Bs[lc * 4 + 3][lr] = bv.w;
        __syncthreads();

#pragma unroll
        for (int kk = 0; kk < 16; kk++) {
            float4 a4 = *(const float4*)&As[kk][ty * 4];
            float4 b4 = *(const float4*)&Bs[kk][tx * 4];
            float af[4] = {a4.x, a4.y, a4.z, a4.w};
            float bf[4] = {b4.x, b4.y, b4.z, b4.w};
#pragma unroll
            for (int i = 0; i < 4; i++)
#pragma unroll
                for (int j = 0; j < 4; j++)
                    acc[i][j] += af[i] * bf[j];
        }
        __syncthreads();
    }

#pragma unroll
    for (int i = 0; i < 4; i++) {
        int row = m0 + ty * 4 + i;
#pragma unroll
        for (int j = 0; j < 4; j++) {
            int col = n0 + tx * 4 + j;
            float b = bias ? bias[col] : 0.f;
            C[(size_t)row * N + col] = acc[i][j] + b;
        }
    }
}

// ---------------------------------------------------------------------------
// RMSNorm(w, eps=1e-6) + interleaved RoPE on g_Q / g_K, in place.
// One warp per (s,h) row of 128; 8 warps per block. blockIdx.y: 0=Q, 1=K.
// ---------------------------------------------------------------------------
__global__ __launch_bounds__(256) void rms_rope(
    const float* __restrict__ cosp, const float* __restrict__ sinp,
    const float* __restrict__ qw, const float* __restrict__ kw)
{
    const int warp = threadIdx.x >> 5;
    const int lane = threadIdx.x & 31;
    const int row = blockIdx.x * 8 + warp;           // 0 .. SEQ*NH-1
    float* X = (blockIdx.y == 0) ? g_Q : g_K;
    const float* w = (blockIdx.y == 0) ? qw : kw;
    const int s = row / NH;
    const size_t base = (size_t)row * HD + lane * 4;

    float4 x = *(const float4*)(X + base);
    float ss = x.x * x.x + x.y * x.y + x.z * x.z + x.w * x.w;
#pragma unroll
    for (int o = 16; o; o >>= 1) ss += __shfl_xor_sync(0xffffffffu, ss, o);
    float inv = rsqrtf(ss * (1.f / HD) + 1e-6f);

    float4 wv = *(const float4*)(w + lane * 4);
    float y0 = x.x * inv * wv.x, y1 = x.y * inv * wv.y;
    float y2 = x.z * inv * wv.z, y3 = x.w * inv * wv.w;

    float4 c  = *(const float4*)(cosp + (size_t)s * HD + lane * 4);
    float4 sn = *(const float4*)(sinp + (size_t)s * HD + lane * 4);
    float4 o;
    o.x = y0 * c.x - y1 * sn.x;
    o.y = y1 * c.y + y0 * sn.y;
    o.z = y2 * c.z - y3 * sn.z;
    o.w = y3 * c.w + y2 * sn.w;
    *(float4*)(X + base) = o;
}

// RMSNorm(eps=1e-5, no weight, no rope) on g_IPK / g_IPV in place.
__global__ __launch_bounds__(256) void ip_rms()
{
    const int warp = threadIdx.x >> 5;
    const int lane = threadIdx.x & 31;
    const int row = blockIdx.x * 8 + warp;           // 0 .. IPT*NH-1
    float* X = (blockIdx.y == 0) ? g_IPK : g_IPV;
    const size_t base = (size_t)row * HD + lane * 4;

    float4 x = *(const float4*)(X + base);
    float ss = x.x * x.x + x.y * x.y + x.z * x.z + x.w * x.w;
#pragma unroll
    for (int o = 16; o; o >>= 1) ss += __shfl_xor_sync(0xffffffffu, ss, o);
    float inv = rsqrtf(ss * (1.f / HD) + 1e-5f);
    x.x *= inv; x.y *= inv; x.z *= inv; x.w *= inv;
    *(float4*)(X + base) = x;
}

// ---------------------------------------------------------------------------
// Fused flash attention (fp32): for each (head, 32-query tile) block,
// phase 0 = main attention over S=2048 keys, phase 1 = IP attention over
// T=128 keys. out = O_main + O_ip. 128 threads; thread owns output column tid.
// ---------------------------------------------------------------------------
__global__ __launch_bounds__(128) void attn_kernel(float* __restrict__ out)
{
    __shared__ float qs[32][132];
    __shared__ float kv[32][132];
    __shared__ float sc[32][36];
    __shared__ float abuf[32];
    __shared__ float lbuf[32];

    const int tid = threadIdx.x;
    const int h = blockIdx.y;
    const int q0 = blockIdx.x * 32;
    const float scale = 0.08838834764831845f;  // 1/sqrt(128)

    // Load Q tile (pre-scaled)
#pragma unroll
    for (int it = 0; it < 8; it++) {
        int idx = it * 128 + tid;
        int r = idx >> 5, c4 = idx & 31;
        float4 v = *(const float4*)(g_Q + (size_t)(q0 + r) * HID + h * HD + c4 * 4);
        v.x *= scale; v.y *= scale; v.z *= scale; v.w *= scale;
        *(float4*)&qs[r][c4 * 4] = v;
    }

    float oacc[32];
#pragma unroll
    for (int i = 0; i < 32; i++) oacc[i] = 0.f;
    float mreg = -1e30f, lreg = 0.f;

    const int jg = tid & 3;     // score col group
    const int ir = tid >> 2;    // score row
    const int c = tid;          // output column
    __syncthreads();

    for (int phase = 0; phase < 2; phase++) {
        const float* Ksrc = phase ? g_IPK : g_K;
        const float* Vsrc = phase ? g_IPV : g_V;
        const int ntiles = phase ? (IPT / 32) : (SEQ / 32);

        for (int t = 0; t < ntiles; t++) {
            const int k0 = t * 32;

            // K tile
#pragma unroll
            for (int it = 0; it < 8; it++) {
                int idx = it * 128 + tid;
                int r = idx >> 5, c4 = idx & 31;
                *(float4*)&kv[r][c4 * 4] =
                    *(const float4*)(Ksrc + (size_t)(k0 + r) * HID + h * HD + c4 * 4);
            }
            __syncthreads();

            // S = q.kT
            float a8[8];
#pragma unroll
            for (int jj = 0; jj < 8; jj++) a8[jj] = 0.f;
            for (int d4 = 0; d4 < HD; d4 += 4) {
                float4 q4 = *(const float4*)&qs[ir][d4];
#pragma unroll
                for (int jj = 0; jj < 8; jj++) {
                    float4 k4 = *(const float4*)&kv[jg * 8 + jj][d4];
                    a8[jj] += q4.x * k4.x + q4.y * k4.y + q4.z * k4.z + q4.w * k4.w;
                }
            }
#pragma unroll
            for (int jj = 0; jj < 8; jj++) sc[ir][jg * 8 + jj] = a8[jj];
            __syncthreads();

            // Online softmax (one thread per query row)
            if (tid < 32) {
                float tm = -1e30f;
#pragma unroll
                for (int j = 0; j < 32; j++) tm = fmaxf(tm, sc[tid][j]);
                float mnew = fmaxf(mreg, tm);
                float alpha = __expf(mreg - mnew);
                float ls = 0.f;
#pragma unroll
                for (int j = 0; j < 32; j++) {
                    float p = __expf(sc[tid][j] - mnew);
                    sc[tid][j] = p;
                    ls += p;
                }
                lreg = lreg * alpha + ls;
                mreg = mnew;
                abuf[tid] = alpha;
            }
            __syncthreads();

            // V tile (reuse kv)
#pragma unroll
            for (int it = 0; it < 8; it++) {
                int idx = it * 128 + tid;
                int r = idx >> 5, c4 = idx & 31;
                *(float4*)&kv[r][c4 * 4] =
                    *(const float4*)(Vsrc + (size_t)(k0 + r) * HID + h * HD + c4 * 4);
            }
            __syncthreads();

            // O += P @ V  (with rescale)
#pragma unroll
            for (int i = 0; i < 32; i++) oacc[i] *= abuf[i];
#pragma unroll
            for (int j4 = 0; j4 < 8; j4++) {
                float v0 = kv[j4 * 4 + 0][c];
                float v1 = kv[j4 * 4 + 1][c];
                float v2 = kv[j4 * 4 + 2][c];
                float v3 = kv[j4 * 4 + 3][c];
#pragma unroll
                for (int i = 0; i < 32; i++) {
                    float4 p4 = *(const float4*)&sc[i][j4 * 4];
                    oacc[i] += p4.x * v0 + p4.y * v1 + p4.z * v2 + p4.w * v3;
                }
            }
            __syncthreads();
        }

        // Finalize this phase
        if (tid < 32) lbuf[tid] = lreg;
        __syncthreads();
        if (phase == 0) {
#pragma unroll
            for (int i = 0; i < 32; i++)
                out[(size_t)(q0 + i) * HID + h * HD + c] = oacc[i] / lbuf[i];
#pragma unroll
            for (int i = 0; i < 32; i++) oacc[i] = 0.f;
            mreg = -1e30f; lreg = 0.f;
        } else {
#pragma unroll
            for (int i = 0; i < 32; i++)
                out[(size_t)(q0 + i) * HID + h * HD + c] += oacc[i] / lbuf[i];
        }
        __syncthreads();
    }
}

// ---------------------------------------------------------------------------
extern "C" void kernel_launch(void* const* d_in, const int* in_sizes, int n_in,
                              void* d_out, int out_size)
{
    const float* hidden = (const float*)d_in[0];
    const float* cosp   = (const float*)d_in[1];
    const float* sinp   = (const float*)d_in[2];
    const float* iph    = (const float*)d_in[3];
    const float* Wq     = (const float*)d_in[4];
    const float* bq     = (const float*)d_in[5];
    const float* Wk     = (const float*)d_in[6];
    const float* bk     = (const float*)d_in[7];
    const float* Wv     = (const float*)d_in[8];
    const float* bv     = (const float*)d_in[9];
    const float* nqw    = (const float*)d_in[10];
    const float* nkw    = (const float*)d_in[11];
    const float* Wkip   = (const float*)d_in[12];
    const float* Wvip   = (const float*)d_in[13];
    float* out = (float*)d_out;

    dim3 gProj(HID / 64, SEQ / 64);
    sgemm_nt<<<gProj, 256>>>(hidden, Wq, bq, 0, SEQ, HID, HID);
    sgemm_nt<<<gProj, 256>>>(hidden, Wk, bk, 1, SEQ, HID, HID);
    sgemm_nt<<<gProj, 256>>>(hidden, Wv, bv, 2, SEQ, HID, HID);

    dim3 gIp(HID / 64, IPT / 64);
    sgemm_nt<<<gIp, 256>>>(iph, Wkip, nullptr, 3, IPT, HID, CAD);
    sgemm_nt<<<gIp, 256>>>(iph, Wvip, nullptr, 4, IPT, HID, CAD);

    rms_rope<<<dim3(SEQ * NH / 8, 2), 256>>>(cosp, sinp, nqw, nkw);
    ip_rms<<<dim3(IPT * NH / 8, 2), 256>>>();

    attn_kernel<<<dim3(SEQ / 32, NH), 128>>>(out);
}

// round 3
// speedup vs baseline: 1.0022x; 1.0000x over previous
#include <cuda_runtime.h>
#include <cstdint>

#define SEQ  2048
#define HID  3072
#define NH   24
#define HD   128
#define CAD  4096
#define IPT  128

// Scratch (static __device__ — no allocation allowed)
__device__ float g_Q[SEQ * HID];
__device__ float g_K[SEQ * HID];
__device__ float g_V[SEQ * HID];
__device__ float g_IPK[IPT * HID];
__device__ float g_IPV[IPT * HID];

// ---------------------------------------------------------------------------
// SGEMM (NT): C[M,N] = A[M,K] @ B[N,K]^T (+ bias). BM=BN=64, BK=16, 256 thr,
// 4x4 per-thread microtile. M,N multiples of 64; K multiple of 16 (true here).
// ---------------------------------------------------------------------------
__global__ __launch_bounds__(256) void sgemm_nt(
    const float* __restrict__ A, const float* __restrict__ B,
    const float* __restrict__ bias, int outSel, int M, int N, int K)
{
    __shared__ float As[16][68];
    __shared__ float Bs[16][68];

    float* C = (outSel == 0) ? g_Q : (outSel == 1) ? g_K :
               (outSel == 2) ? g_V : (outSel == 3) ? g_IPK : g_IPV;

    const int tid = threadIdx.x;
    const int tx = tid & 15;
    const int ty = tid >> 4;
    const int m0 = blockIdx.y * 64;
    const int n0 = blockIdx.x * 64;
    const int lr = tid >> 2;     // 0..63
    const int lc = tid & 3;      // 0..3

    float acc[4][4];
#pragma unroll
    for (int i = 0; i < 4; i++)
#pragma unroll
        for (int j = 0; j < 4; j++) acc[i][j] = 0.f;

    const float* Arow = A + (size_t)(m0 + lr) * K + lc * 4;
    const float* Brow = B + (size_t)(n0 + lr) * K + lc * 4;

    for (int k0 = 0; k0 < K; k0 += 16) {
        float4 av = *(const float4*)(Arow + k0);
        float4 bv = *(const float4*)(Brow + k0);
        As[lc * 4 + 0][lr] = av.x; As[lc * 4 + 1][lr] = av.y;
        As[lc * 4 + 2][lr] = av.z; As[lc * 4 + 3][lr] = av.w;
        Bs[lc * 4 + 0][lr] = bv.x; Bs[lc * 4 + 1][lr] = bv.y;
        Bs[lc * 4 + 2][lr] = bv.z; Bs[lc * 4 + 3][lr] = bv.w;
        __syncthreads();

#pragma unroll
        for (int kk = 0; kk < 16; kk++) {
            float4 a4 = *(const float4*)&As[kk][ty * 4];
            float4 b4 = *(const float4*)&Bs[kk][tx * 4];
            float af[4] = {a4.x, a4.y, a4.z, a4.w};
            float bf[4] = {b4.x, b4.y, b4.z, b4.w};
#pragma unroll
            for (int i = 0; i < 4; i++)
#pragma unroll
                for (int j = 0; j < 4; j++)
                    acc[i][j] += af[i] * bf[j];
        }
        __syncthreads();
    }

#pragma unroll
    for (int i = 0; i < 4; i++) {
        int row = m0 + ty * 4 + i;
#pragma unroll
        for (int j = 0; j < 4; j++) {
            int col = n0 + tx * 4 + j;
            float b = bias ? bias[col] : 0.f;
            C[(size_t)row * N + col] = acc[i][j] + b;
        }
    }
}

// ---------------------------------------------------------------------------
// RMSNorm(w, eps=1e-6) + interleaved RoPE on g_Q / g_K, in place.
// One warp per (s,h) row of 128; 8 warps per block. blockIdx.y: 0=Q, 1=K.
// ---------------------------------------------------------------------------
__global__ __launch_bounds__(256) void rms_rope(
    const float* __restrict__ cosp, const float* __restrict__ sinp,
    const float* __restrict__ qw, const float* __restrict__ kw)
{
    const int warp = threadIdx.x >> 5;
    const int lane = threadIdx.x & 31;
    const int row = blockIdx.x * 8 + warp;           // 0 .. SEQ*NH-1
    float* X = (blockIdx.y == 0) ? g_Q : g_K;
    const float* w = (blockIdx.y == 0) ? qw : kw;
    const int s = row / NH;
    const size_t base = (size_t)row * HD + lane * 4;

    float4 x = *(const float4*)(X + base);
    float ss = x.x * x.x + x.y * x.y + x.z * x.z + x.w * x.w;
#pragma unroll
    for (int o = 16; o; o >>= 1) ss += __shfl_xor_sync(0xffffffffu, ss, o);
    float inv = rsqrtf(ss * (1.f / HD) + 1e-6f);

    float4 wv = *(const float4*)(w + lane * 4);
    float y0 = x.x * inv * wv.x, y1 = x.y * inv * wv.y;
    float y2 = x.z * inv * wv.z, y3 = x.w * inv * wv.w;

    float4 c  = *(const float4*)(cosp + (size_t)s * HD + lane * 4);
    float4 sn = *(const float4*)(sinp + (size_t)s * HD + lane * 4);
    float4 o;
    o.x = y0 * c.x - y1 * sn.x;
    o.y = y1 * c.y + y0 * sn.y;
    o.z = y2 * c.z - y3 * sn.z;
    o.w = y3 * c.w + y2 * sn.w;
    *(float4*)(X + base) = o;
}

// RMSNorm(eps=1e-5, no weight, no rope) on g_IPK / g_IPV in place.
__global__ __launch_bounds__(256) void ip_rms()
{
    const int warp = threadIdx.x >> 5;
    const int lane = threadIdx.x & 31;
    const int row = blockIdx.x * 8 + warp;           // 0 .. IPT*NH-1
    float* X = (blockIdx.y == 0) ? g_IPK : g_IPV;
    const size_t base = (size_t)row * HD + lane * 4;

    float4 x = *(const float4*)(X + base);
    float ss = x.x * x.x + x.y * x.y + x.z * x.z + x.w * x.w;
#pragma unroll
    for (int o = 16; o; o >>= 1) ss += __shfl_xor_sync(0xffffffffu, ss, o);
    float inv = rsqrtf(ss * (1.f / HD) + 1e-5f);
    x.x *= inv; x.y *= inv; x.z *= inv; x.w *= inv;
    *(float4*)(X + base) = x;
}

// ---------------------------------------------------------------------------
// Fused flash attention (fp32): for each (head, 32-query tile) block,
// phase 0 = main attention over S=2048 keys, phase 1 = IP attention over
// T=128 keys. out = O_main + O_ip. 128 threads; thread owns output column tid.
// ---------------------------------------------------------------------------
__global__ __launch_bounds__(128) void attn_kernel(float* __restrict__ out)
{
    __shared__ float qs[32][132];
    __shared__ float kv[32][132];
    __shared__ float sc[32][36];
    __shared__ float abuf[32];
    __shared__ float lbuf[32];

    const int tid = threadIdx.x;
    const int h = blockIdx.y;
    const int q0 = blockIdx.x * 32;
    const float scale = 0.08838834764831845f;  // 1/sqrt(128)

    // Load Q tile (pre-scaled)
#pragma unroll
    for (int it = 0; it < 8; it++) {
        int idx = it * 128 + tid;
        int r = idx >> 5, c4 = idx & 31;
        float4 v = *(const float4*)(g_Q + (size_t)(q0 + r) * HID + h * HD + c4 * 4);
        v.x *= scale; v.y *= scale; v.z *= scale; v.w *= scale;
        *(float4*)&qs[r][c4 * 4] = v;
    }

    float oacc[32];
#pragma unroll
    for (int i = 0; i < 32; i++) oacc[i] = 0.f;
    float mreg = -1e30f, lreg = 0.f;

    const int jg = tid & 3;     // score col group
    const int ir = tid >> 2;    // score row
    const int c = tid;          // output column
    __syncthreads();

    for (int phase = 0; phase < 2; phase++) {
        const float* Ksrc = phase ? g_IPK : g_K;
        const float* Vsrc = phase ? g_IPV : g_V;
        const int ntiles = phase ? (IPT / 32) : (SEQ / 32);

        for (int t = 0; t < ntiles; t++) {
            const int k0 = t * 32;

            // K tile
#pragma unroll
            for (int it = 0; it < 8; it++) {
                int idx = it * 128 + tid;
                int r = idx >> 5, c4 = idx & 31;
                *(float4*)&kv[r][c4 * 4] =
                    *(const float4*)(Ksrc + (size_t)(k0 + r) * HID + h * HD + c4 * 4);
            }
            __syncthreads();

            // S = q.kT
            float a8[8];
#pragma unroll
            for (int jj = 0; jj < 8; jj++) a8[jj] = 0.f;
            for (int d4 = 0; d4 < HD; d4 += 4) {
                float4 q4 = *(const float4*)&qs[ir][d4];
#pragma unroll
                for (int jj = 0; jj < 8; jj++) {
                    float4 k4 = *(const float4*)&kv[jg * 8 + jj][d4];
                    a8[jj] += q4.x * k4.x + q4.y * k4.y + q4.z * k4.z + q4.w * k4.w;
                }
            }
#pragma unroll
            for (int jj = 0; jj < 8; jj++) sc[ir][jg * 8 + jj] = a8[jj];
            __syncthreads();

            // Online softmax (one thread per query row)
            if (tid < 32) {
                float tm = -1e30f;
#pragma unroll
                for (int j = 0; j < 32; j++) tm = fmaxf(tm, sc[tid][j]);
                float mnew = fmaxf(mreg, tm);
                float alpha = __expf(mreg - mnew);
                float ls = 0.f;
#pragma unroll
                for (int j = 0; j < 32; j++) {
                    float p = __expf(sc[tid][j] - mnew);
                    sc[tid][j] = p;
                    ls += p;
                }
                lreg = lreg * alpha + ls;
                mreg = mnew;
                abuf[tid] = alpha;
            }
            __syncthreads();

            // V tile (reuse kv)
#pragma unroll
            for (int it = 0; it < 8; it++) {
                int idx = it * 128 + tid;
                int r = idx >> 5, c4 = idx & 31;
                *(float4*)&kv[r][c4 * 4] =
                    *(const float4*)(Vsrc + (size_t)(k0 + r) * HID + h * HD + c4 * 4);
            }
            __syncthreads();

            // O += P @ V  (with rescale)
#pragma unroll
            for (int i = 0; i < 32; i++) oacc[i] *= abuf[i];
#pragma unroll
            for (int j4 = 0; j4 < 8; j4++) {
                float v0 = kv[j4 * 4 + 0][c];
                float v1 = kv[j4 * 4 + 1][c];
                float v2 = kv[j4 * 4 + 2][c];
                float v3 = kv[j4 * 4 + 3][c];
#pragma unroll
                for (int i = 0; i < 32; i++) {
                    float4 p4 = *(const float4*)&sc[i][j4 * 4];
                    oacc[i] += p4.x * v0 + p4.y * v1 + p4.z * v2 + p4.w * v3;
                }
            }
            __syncthreads();
        }

        // Finalize this phase
        if (tid < 32) lbuf[tid] = lreg;
        __syncthreads();
        if (phase == 0) {
#pragma unroll
            for (int i = 0; i < 32; i++)
                out[(size_t)(q0 + i) * HID + h * HD + c] = oacc[i] / lbuf[i];
#pragma unroll
            for (int i = 0; i < 32; i++) oacc[i] = 0.f;
            mreg = -1e30f; lreg = 0.f;
        } else {
#pragma unroll
            for (int i = 0; i < 32; i++)
                out[(size_t)(q0 + i) * HID + h * HD + c] += oacc[i] / lbuf[i];
        }
        __syncthreads();
    }
}

// ---------------------------------------------------------------------------
extern "C" void kernel_launch(void* const* d_in, const int* in_sizes, int n_in,
                              void* d_out, int out_size)
{
    const float* hidden = (const float*)d_in[0];
    const float* cosp   = (const float*)d_in[1];
    const float* sinp   = (const float*)d_in[2];
    const float* iph    = (const float*)d_in[3];
    const float* Wq     = (const float*)d_in[4];
    const float* bq     = (const float*)d_in[5];
    const float* Wk     = (const float*)d_in[6];
    const float* bk     = (const float*)d_in[7];
    const float* Wv     = (const float*)d_in[8];
    const float* bv     = (const float*)d_in[9];
    const float* nqw    = (const float*)d_in[10];
    const float* nkw    = (const float*)d_in[11];
    const float* Wkip   = (const float*)d_in[12];
    const float* Wvip   = (const float*)d_in[13];
    float* out = (float*)d_out;

    dim3 gProj(HID / 64, SEQ / 64);
    sgemm_nt<<<gProj, 256>>>(hidden, Wq, bq, 0, SEQ, HID, HID);
    sgemm_nt<<<gProj, 256>>>(hidden, Wk, bk, 1, SEQ, HID, HID);
    sgemm_nt<<<gProj, 256>>>(hidden, Wv, bv, 2, SEQ, HID, HID);

    dim3 gIp(HID / 64, IPT / 64);
    sgemm_nt<<<gIp, 256>>>(iph, Wkip, nullptr, 3, IPT, HID, CAD);
    sgemm_nt<<<gIp, 256>>>(iph, Wvip, nullptr, 4, IPT, HID, CAD);

    rms_rope<<<dim3(SEQ * NH / 8, 2), 256>>>(cosp, sinp, nqw, nkw);
    ip_rms<<<dim3(IPT * NH / 8, 2), 256>>>();

    attn_kernel<<<dim3(SEQ / 32, NH), 128>>>(out);
}

// round 5
// speedup vs baseline: 1.1615x; 1.1590x over previous
#include <cuda_runtime.h>
#include <cuda_bf16.h>
#include <cstdint>

#define SEQ  2048
#define HID  3072
#define NH   24
#define HD   128
#define CAD  4096
#define IPT  128

// ---------------- scratch (static __device__ — no allocation allowed) ------
__device__ float g_Q[SEQ * HID];
__device__ float g_K[SEQ * HID];
__device__ float g_V[SEQ * HID];
__device__ float g_IPK[IPT * HID];
__device__ float g_IPV[IPT * HID];

// bf16 hi/lo splits of all GEMM operands
__device__ __nv_bfloat16 g_Hh[SEQ * HID],  g_Hl[SEQ * HID];
__device__ __nv_bfloat16 g_Wqh[HID * HID], g_Wql[HID * HID];
__device__ __nv_bfloat16 g_Wkh[HID * HID], g_Wkl[HID * HID];
__device__ __nv_bfloat16 g_Wvh[HID * HID], g_Wvl[HID * HID];
__device__ __nv_bfloat16 g_IPHh[IPT * CAD], g_IPHl[IPT * CAD];
__device__ __nv_bfloat16 g_WKiph[HID * CAD], g_WKipl[HID * CAD];
__device__ __nv_bfloat16 g_WViph[HID * CAD], g_WVipl[HID * CAD];

// ---------------- asm helpers (all plain-sm_103-legal) ----------------------
__device__ __forceinline__ uint32_t smem_u32(const void* p) {
    uint32_t a;
    asm("{ .reg .u64 t; cvta.to.shared.u64 t, %1; cvt.u32.u64 %0, t; }"
        : "=r"(a) : "l"(p));
    return a;
}

#define CP_ASYNC_CG(sm, gm) \
    asm volatile("cp.async.cg.shared.global [%0], [%1], 16;" :: "r"(sm), "l"(gm))
#define CP_COMMIT() asm volatile("cp.async.commit_group;" ::: "memory")
#define CP_WAIT1()  asm volatile("cp.async.wait_group 1;" ::: "memory")
#define CP_WAIT0()  asm volatile("cp.async.wait_group 0;" ::: "memory")

#define LDMATRIX_X4(r0, r1, r2, r3, addr) \
    asm volatile("ldmatrix.sync.aligned.m8n8.x4.shared.b16 {%0,%1,%2,%3}, [%4];" \
        : "=r"(r0), "=r"(r1), "=r"(r2), "=r"(r3) : "r"(addr))

#define MMA16816(d, a0, a1, a2, a3, b0, b1) \
    asm volatile("mma.sync.aligned.m16n8k16.row.col.f32.bf16.bf16.f32 " \
        "{%0,%1,%2,%3},{%4,%5,%6,%7},{%8,%9},{%0,%1,%2,%3};" \
        : "+f"((d)[0]), "+f"((d)[1]), "+f"((d)[2]), "+f"((d)[3]) \
        : "r"(a0), "r"(a1), "r"(a2), "r"(a3), "r"(b0), "r"(b1))

// ---------------------------------------------------------------------------
// fp32 -> (bf16 hi, bf16 lo) split, 4 elems/thread
// ---------------------------------------------------------------------------
__global__ __launch_bounds__(256) void split_bf16(
    const float4* __restrict__ src, __nv_bfloat162* __restrict__ hi,
    __nv_bfloat162* __restrict__ lo, int n4)
{
    int i = blockIdx.x * 256 + threadIdx.x;
    if (i >= n4) return;
    float4 v = src[i];
    __nv_bfloat16 h0 = __float2bfloat16(v.x), h1 = __float2bfloat16(v.y);
    __nv_bfloat16 h2 = __float2bfloat16(v.z), h3 = __float2bfloat16(v.w);
    __nv_bfloat16 l0 = __float2bfloat16(v.x - __bfloat162float(h0));
    __nv_bfloat16 l1 = __float2bfloat16(v.y - __bfloat162float(h1));
    __nv_bfloat16 l2 = __float2bfloat16(v.z - __bfloat162float(h2));
    __nv_bfloat16 l3 = __float2bfloat16(v.w - __bfloat162float(h3));
    hi[2 * i]     = __halves2bfloat162(h0, h1);
    hi[2 * i + 1] = __halves2bfloat162(h2, h3);
    lo[2 * i]     = __halves2bfloat162(l0, l1);
    lo[2 * i + 1] = __halves2bfloat162(l2, l3);
}

// ---------------------------------------------------------------------------
// HMMA GEMM (NT): C[M,N] = A[M,K] @ B[N,K]^T + bias, 3-term bf16 split.
// BM=BN=128, BK=32, 256 thr (2x4 warps, 64x32 per warp), cp.async dbl-buffer.
// ---------------------------------------------------------------------------
#define BK 32
#define SSTR 40  // smem row stride in bf16 (80 bytes: 16B-aligned, ldmatrix conflict-free)

__global__ __launch_bounds__(256) void gemm_mma(
    const __nv_bfloat16* __restrict__ Ah, const __nv_bfloat16* __restrict__ Al,
    const __nv_bfloat16* __restrict__ Bh, const __nv_bfloat16* __restrict__ Bl,
    const float* __restrict__ bias, int outSel, int M, int N, int K)
{
    __shared__ __align__(16) __nv_bfloat16 sA[2][128][SSTR];
    __shared__ __align__(16) __nv_bfloat16 sB[2][128][SSTR];

    float* C = (outSel == 0) ? g_Q : (outSel == 1) ? g_K :
               (outSel == 2) ? g_V : (outSel == 3) ? g_IPK : g_IPV;

    const int tid = threadIdx.x;
    const int wid = tid >> 5;
    const int lane = tid & 31;
    const int warp_m = wid >> 2;       // 0..1
    const int warp_n = wid & 3;        // 0..3
    const int m0 = blockIdx.y * 128;
    const int n0 = blockIdx.x * 128;

    // per-thread global->smem copy coords: one row, one 32B segment (2x16B)
    const int cprow = tid >> 1;              // 0..127
    const int cpg   = (tid & 1) * 2;         // 0 or 2 (16B group index)

    const uint32_t sAu = smem_u32(&sA[0][0][0]);
    const uint32_t sBu = smem_u32(&sB[0][0][0]);
    const uint32_t stageBytes = 128 * SSTR * 2;
    const uint32_t sA_dst = sAu + (uint32_t)(cprow * SSTR + cpg * 8) * 2;
    const uint32_t sB_dst = sBu + (uint32_t)(cprow * SSTR + cpg * 8) * 2;

    // ldmatrix source addresses (lane-dependent)
    const int a_row = lane & 15;
    const int a_k   = (lane >> 4) * 8;
    const int b_row = ((lane >> 4) & 1) * 8 + (lane & 7);
    const int b_k   = ((lane >> 3) & 1) * 8;

    float acc[4][4][4];
#pragma unroll
    for (int i = 0; i < 4; i++)
#pragma unroll
        for (int j = 0; j < 4; j++)
#pragma unroll
            for (int e = 0; e < 4; e++) acc[i][j][e] = 0.f;

    const int nkc = K / BK;
    const int NC = 3 * nkc;

    // chunk source pointers: term 0: Ah.Bh, term 1: Al.Bh, term 2: Ah.Bl
    auto srcA = [&](int c) -> const __nv_bfloat16* {
        int t = c / nkc; return (t == 1) ? Al : Ah;
    };
    auto srcB = [&](int c) -> const __nv_bfloat16* {
        int t = c / nkc; return (t == 2) ? Bl : Bh;
    };
    auto koff = [&](int c) -> int { return (c % nkc) * BK; };

    // prefetch chunk 0 into stage 0
    {
        const __nv_bfloat16* Ap = srcA(0) + (size_t)(m0 + cprow) * K + koff(0) + cpg * 8;
        const __nv_bfloat16* Bp = srcB(0) + (size_t)(n0 + cprow) * K + koff(0) + cpg * 8;
        CP_ASYNC_CG(sA_dst, Ap);
        CP_ASYNC_CG(sA_dst + 16, Ap + 8);
        CP_ASYNC_CG(sB_dst, Bp);
        CP_ASYNC_CG(sB_dst + 16, Bp + 8);
        CP_COMMIT();
    }

    for (int c = 0; c < NC; c++) {
        const int s = c & 1;
        if (c + 1 < NC) {
            const int s2 = (c + 1) & 1;
            const __nv_bfloat16* Ap = srcA(c + 1) + (size_t)(m0 + cprow) * K + koff(c + 1) + cpg * 8;
            const __nv_bfloat16* Bp = srcB(c + 1) + (size_t)(n0 + cprow) * K + koff(c + 1) + cpg * 8;
            CP_ASYNC_CG(sA_dst + s2 * stageBytes, Ap);
            CP_ASYNC_CG(sA_dst + s2 * stageBytes + 16, Ap + 8);
            CP_ASYNC_CG(sB_dst + s2 * stageBytes, Bp);
            CP_ASYNC_CG(sB_dst + s2 * stageBytes + 16, Bp + 8);
            CP_COMMIT();
            CP_WAIT1();
        } else {
            CP_WAIT0();
        }
        __syncthreads();

        const uint32_t aS = sAu + s * stageBytes;
        const uint32_t bS = sBu + s * stageBytes;

#pragma unroll
        for (int ks = 0; ks < 2; ks++) {
            uint32_t afr[4][4];
#pragma unroll
            for (int ma = 0; ma < 4; ma++) {
                uint32_t addr = aS + (uint32_t)((warp_m * 64 + ma * 16 + a_row) * SSTR
                                                + ks * 16 + a_k) * 2;
                LDMATRIX_X4(afr[ma][0], afr[ma][1], afr[ma][2], afr[ma][3], addr);
            }
            uint32_t bfr[4][2];
#pragma unroll
            for (int np = 0; np < 2; np++) {   // pairs of n8 tiles
                uint32_t addr = bS + (uint32_t)((warp_n * 32 + np * 16 + b_row) * SSTR
                                                + ks * 16 + b_k) * 2;
                uint32_t r0, r1, r2, r3;
                LDMATRIX_X4(r0, r1, r2, r3, addr);
                bfr[np * 2][0] = r0;     bfr[np * 2][1] = r1;
                bfr[np * 2 + 1][0] = r2; bfr[np * 2 + 1][1] = r3;
            }
#pragma unroll
            for (int ma = 0; ma < 4; ma++)
#pragma unroll
                for (int nb = 0; nb < 4; nb++)
                    MMA16816(acc[ma][nb], afr[ma][0], afr[ma][1], afr[ma][2], afr[ma][3],
                             bfr[nb][0], bfr[nb][1]);
        }
        __syncthreads();
    }

    // epilogue
    const int er = m0 + warp_m * 64 + (lane >> 2);
    const int ec = n0 + warp_n * 32 + (lane & 3) * 2;
#pragma unroll
    for (int ma = 0; ma < 4; ma++) {
        int row = er + ma * 16;
#pragma unroll
        for (int nb = 0; nb < 4; nb++) {
            int col = ec + nb * 8;
            float b0 = bias ? bias[col] : 0.f;
            float b1 = bias ? bias[col + 1] : 0.f;
            C[(size_t)row * N + col]           = acc[ma][nb][0] + b0;
            C[(size_t)row * N + col + 1]       = acc[ma][nb][1] + b1;
            C[(size_t)(row + 8) * N + col]     = acc[ma][nb][2] + b0;
            C[(size_t)(row + 8) * N + col + 1] = acc[ma][nb][3] + b1;
        }
    }
}

// ---------------------------------------------------------------------------
// RMSNorm + interleaved RoPE on g_Q / g_K
// ---------------------------------------------------------------------------
__global__ __launch_bounds__(256) void rms_rope(
    const float* __restrict__ cosp, const float* __restrict__ sinp,
    const float* __restrict__ qw, const float* __restrict__ kw)
{
    const int warp = threadIdx.x >> 5;
    const int lane = threadIdx.x & 31;
    const int row = blockIdx.x * 8 + warp;
    float* X = (blockIdx.y == 0) ? g_Q : g_K;
    const float* w = (blockIdx.y == 0) ? qw : kw;
    const int s = row / NH;
    const size_t base = (size_t)row * HD + lane * 4;

    float4 x = *(const float4*)(X + base);
    float ss = x.x * x.x + x.y * x.y + x.z * x.z + x.w * x.w;
#pragma unroll
    for (int o = 16; o; o >>= 1) ss += __shfl_xor_sync(0xffffffffu, ss, o);
    float inv = rsqrtf(ss * (1.f / HD) + 1e-6f);

    float4 wv = *(const float4*)(w + lane * 4);
    float y0 = x.x * inv * wv.x, y1 = x.y * inv * wv.y;
    float y2 = x.z * inv * wv.z, y3 = x.w * inv * wv.w;

    float4 c  = *(const float4*)(cosp + (size_t)s * HD + lane * 4);
    float4 sn = *(const float4*)(sinp + (size_t)s * HD + lane * 4);
    float4 o;
    o.x = y0 * c.x - y1 * sn.x;
    o.y = y1 * c.y + y0 * sn.y;
    o.z = y2 * c.z - y3 * sn.z;
    o.w = y3 * c.w + y2 * sn.w;
    *(float4*)(X + base) = o;
}

__global__ __launch_bounds__(256) void ip_rms()
{
    const int warp = threadIdx.x >> 5;
    const int lane = threadIdx.x & 31;
    const int row = blockIdx.x * 8 + warp;
    float* X = (blockIdx.y == 0) ? g_IPK : g_IPV;
    const size_t base = (size_t)row * HD + lane * 4;

    float4 x = *(const float4*)(X + base);
    float ss = x.x * x.x + x.y * x.y + x.z * x.z + x.w * x.w;
#pragma unroll
    for (int o = 16; o; o >>= 1) ss += __shfl_xor_sync(0xffffffffu, ss, o);
    float inv = rsqrtf(ss * (1.f / HD) + 1e-5f);
    x.x *= inv; x.y *= inv; x.z *= inv; x.w *= inv;
    *(float4*)(X + base) = x;
}

// ---------------------------------------------------------------------------
// Fused fp32 flash attention (unchanged — passed at rel_err 2e-6)
// ---------------------------------------------------------------------------
__global__ __launch_bounds__(128) void attn_kernel(float* __restrict__ out)
{
    __shared__ float qs[32][132];
    __shared__ float kv[32][132];
    __shared__ float sc[32][36];
    __shared__ float abuf[32];
    __shared__ float lbuf[32];

    const int tid = threadIdx.x;
    const int h = blockIdx.y;
    const int q0 = blockIdx.x * 32;
    const float scale = 0.08838834764831845f;

#pragma unroll
    for (int it = 0; it < 8; it++) {
        int idx = it * 128 + tid;
        int r = idx >> 5, c4 = idx & 31;
        float4 v = *(const float4*)(g_Q + (size_t)(q0 + r) * HID + h * HD + c4 * 4);
        v.x *= scale; v.y *= scale; v.z *= scale; v.w *= scale;
        *(float4*)&qs[r][c4 * 4] = v;
    }

    float oacc[32];
#pragma unroll
    for (int i = 0; i < 32; i++) oacc[i] = 0.f;
    float mreg = -1e30f, lreg = 0.f;

    const int jg = tid & 3;
    const int ir = tid >> 2;
    const int c = tid;
    __syncthreads();

    for (int phase = 0; phase < 2; phase++) {
        const float* Ksrc = phase ? g_IPK : g_K;
        const float* Vsrc = phase ? g_IPV : g_V;
        const int ntiles = phase ? (IPT / 32) : (SEQ / 32);

        for (int t = 0; t < ntiles; t++) {
            const int k0 = t * 32;
#pragma unroll
            for (int it = 0; it < 8; it++) {
                int idx = it * 128 + tid;
                int r = idx >> 5, c4 = idx & 31;
                *(float4*)&kv[r][c4 * 4] =
                    *(const float4*)(Ksrc + (size_t)(k0 + r) * HID + h * HD + c4 * 4);
            }
            __syncthreads();

            float a8[8];
#pragma unroll
            for (int jj = 0; jj < 8; jj++) a8[jj] = 0.f;
            for (int d4 = 0; d4 < HD; d4 += 4) {
                float4 q4 = *(const float4*)&qs[ir][d4];
#pragma unroll
                for (int jj = 0; jj < 8; jj++) {
                    float4 k4 = *(const float4*)&kv[jg * 8 + jj][d4];
                    a8[jj] += q4.x * k4.x + q4.y * k4.y + q4.z * k4.z + q4.w * k4.w;
                }
            }
#pragma unroll
            for (int jj = 0; jj < 8; jj++) sc[ir][jg * 8 + jj] = a8[jj];
            __syncthreads();

            if (tid < 32) {
                float tm = -1e30f;
#pragma unroll
                for (int j = 0; j < 32; j++) tm = fmaxf(tm, sc[tid][j]);
                float mnew = fmaxf(mreg, tm);
                float alpha = __expf(mreg - mnew);
                float ls = 0.f;
#pragma unroll
                for (int j = 0; j < 32; j++) {
                    float p = __expf(sc[tid][j] - mnew);
                    sc[tid][j] = p;
                    ls += p;
                }
                lreg = lreg * alpha + ls;
                mreg = mnew;
                abuf[tid] = alpha;
            }
            __syncthreads();

#pragma unroll
            for (int it = 0; it < 8; it++) {
                int idx = it * 128 + tid;
                int r = idx >> 5, c4 = idx & 31;
                *(float4*)&kv[r][c4 * 4] =
                    *(const float4*)(Vsrc + (size_t)(k0 + r) * HID + h * HD + c4 * 4);
            }
            __syncthreads();

#pragma unroll
            for (int i = 0; i < 32; i++) oacc[i] *= abuf[i];
#pragma unroll
            for (int j4 = 0; j4 < 8; j4++) {
                float v0 = kv[j4 * 4 + 0][c];
                float v1 = kv[j4 * 4 + 1][c];
                float v2 = kv[j4 * 4 + 2][c];
                float v3 = kv[j4 * 4 + 3][c];
#pragma unroll
                for (int i = 0; i < 32; i++) {
                    float4 p4 = *(const float4*)&sc[i][j4 * 4];
                    oacc[i] += p4.x * v0 + p4.y * v1 + p4.z * v2 + p4.w * v3;
                }
            }
            __syncthreads();
        }

        if (tid < 32) lbuf[tid] = lreg;
        __syncthreads();
        if (phase == 0) {
#pragma unroll
            for (int i = 0; i < 32; i++)
                out[(size_t)(q0 + i) * HID + h * HD + c] = oacc[i] / lbuf[i];
#pragma unroll
            for (int i = 0; i < 32; i++) oacc[i] = 0.f;
            mreg = -1e30f; lreg = 0.f;
        } else {
#pragma unroll
            for (int i = 0; i < 32; i++)
                out[(size_t)(q0 + i) * HID + h * HD + c] += oacc[i] / lbuf[i];
        }
        __syncthreads();
    }
}

// ---------------------------------------------------------------------------
extern "C" void kernel_launch(void* const* d_in, const int* in_sizes, int n_in,
                              void* d_out, int out_size)
{
    const float* hidden = (const float*)d_in[0];
    const float* cosp   = (const float*)d_in[1];
    const float* sinp   = (const float*)d_in[2];
    const float* iph    = (const float*)d_in[3];
    const float* Wq     = (const float*)d_in[4];
    const float* bq     = (const float*)d_in[5];
    const float* Wk     = (const float*)d_in[6];
    const float* bk     = (const float*)d_in[7];
    const float* Wv     = (const float*)d_in[8];
    const float* bv     = (const float*)d_in[9];
    const float* nqw    = (const float*)d_in[10];
    const float* nkw    = (const float*)d_in[11];
    const float* Wkip   = (const float*)d_in[12];
    const float* Wvip   = (const float*)d_in[13];
    float* out = (float*)d_out;

    __nv_bfloat16 *Hh, *Hl, *Wqh, *Wql, *Wkh, *Wkl, *Wvh, *Wvl;
    __nv_bfloat16 *IPHh, *IPHl, *WKiph, *WKipl, *WViph, *WVipl;
    cudaGetSymbolAddress((void**)&Hh, g_Hh);     cudaGetSymbolAddress((void**)&Hl, g_Hl);
    cudaGetSymbolAddress((void**)&Wqh, g_Wqh);   cudaGetSymbolAddress((void**)&Wql, g_Wql);
    cudaGetSymbolAddress((void**)&Wkh, g_Wkh);   cudaGetSymbolAddress((void**)&Wkl, g_Wkl);
    cudaGetSymbolAddress((void**)&Wvh, g_Wvh);   cudaGetSymbolAddress((void**)&Wvl, g_Wvl);
    cudaGetSymbolAddress((void**)&IPHh, g_IPHh); cudaGetSymbolAddress((void**)&IPHl, g_IPHl);
    cudaGetSymbolAddress((void**)&WKiph, g_WKiph); cudaGetSymbolAddress((void**)&WKipl, g_WKipl);
    cudaGetSymbolAddress((void**)&WViph, g_WViph); cudaGetSymbolAddress((void**)&WVipl, g_WVipl);

    auto split = [](const float* s, __nv_bfloat16* h, __nv_bfloat16* l, int n) {
        int n4 = n / 4;
        split_bf16<<<(n4 + 255) / 256, 256>>>((const float4*)s,
            (__nv_bfloat162*)h, (__nv_bfloat162*)l, n4);
    };
    split(hidden, Hh, Hl, SEQ * HID);
    split(Wq, Wqh, Wql, HID * HID);
    split(Wk, Wkh, Wkl, HID * HID);
    split(Wv, Wvh, Wvl, HID * HID);
    split(iph, IPHh, IPHl, IPT * CAD);
    split(Wkip, WKiph, WKipl, HID * CAD);
    split(Wvip, WViph, WVipl, HID * CAD);

    dim3 gMain(HID / 128, SEQ / 128);
    gemm_mma<<<gMain, 256>>>(Hh, Hl, Wqh, Wql, bq, 0, SEQ, HID, HID);
    gemm_mma<<<gMain, 256>>>(Hh, Hl, Wkh, Wkl, bk, 1, SEQ, HID, HID);
    gemm_mma<<<gMain, 256>>>(Hh, Hl, Wvh, Wvl, bv, 2, SEQ, HID, HID);

    dim3 gIp(HID / 128, IPT / 128);
    gemm_mma<<<gIp, 256>>>(IPHh, IPHl, WKiph, WKipl, nullptr, 3, IPT, HID, CAD);
    gemm_mma<<<gIp, 256>>>(IPHh, IPHl, WViph, WVipl, nullptr, 4, IPT, HID, CAD);

    rms_rope<<<dim3(SEQ * NH / 8, 2), 256>>>(cosp, sinp, nqw, nkw);
    ip_rms<<<dim3(IPT * NH / 8, 2), 256>>>();

    attn_kernel<<<dim3(SEQ / 32, NH), 128>>>(out);
}

// round 6
// speedup vs baseline: 1.2672x; 1.0910x over previous
#include <cuda_runtime.h>
#include <cuda_bf16.h>
#include <cstdint>

#define SEQ  2048
#define HID  3072
#define NH   24
#define HD   128
#define CAD  4096
#define IPT  128

// ---------------- scratch (static __device__ — no allocation allowed) ------
__device__ float g_Q[SEQ * HID];
__device__ float g_K[SEQ * HID];
__device__ float g_V[SEQ * HID];
__device__ float g_IPK[IPT * HID];
__device__ float g_IPV[IPT * HID];

// bf16 hi/lo splits of all GEMM operands
__device__ __nv_bfloat16 g_Hh[SEQ * HID],  g_Hl[SEQ * HID];
__device__ __nv_bfloat16 g_Wqh[HID * HID], g_Wql[HID * HID];
__device__ __nv_bfloat16 g_Wkh[HID * HID], g_Wkl[HID * HID];
__device__ __nv_bfloat16 g_Wvh[HID * HID], g_Wvl[HID * HID];
__device__ __nv_bfloat16 g_IPHh[IPT * CAD], g_IPHl[IPT * CAD];
__device__ __nv_bfloat16 g_WKiph[HID * CAD], g_WKipl[HID * CAD];
__device__ __nv_bfloat16 g_WViph[HID * CAD], g_WVipl[HID * CAD];

// ---------------- asm helpers (all plain-sm_103-legal) ----------------------
__device__ __forceinline__ uint32_t smem_u32(const void* p) {
    uint32_t a;
    asm("{ .reg .u64 t; cvta.to.shared.u64 t, %1; cvt.u32.u64 %0, t; }"
        : "=r"(a) : "l"(p));
    return a;
}

#define CP_ASYNC_CG(sm, gm) \
    asm volatile("cp.async.cg.shared.global [%0], [%1], 16;" :: "r"(sm), "l"(gm))
#define CP_COMMIT() asm volatile("cp.async.commit_group;" ::: "memory")
#define CP_WAIT2()  asm volatile("cp.async.wait_group 2;" ::: "memory")
#define CP_WAIT0()  asm volatile("cp.async.wait_group 0;" ::: "memory")

#define LDMATRIX_X4(r0, r1, r2, r3, addr) \
    asm volatile("ldmatrix.sync.aligned.m8n8.x4.shared.b16 {%0,%1,%2,%3}, [%4];" \
        : "=r"(r0), "=r"(r1), "=r"(r2), "=r"(r3) : "r"(addr))

#define MMA16816(d, a0, a1, a2, a3, b0, b1) \
    asm volatile("mma.sync.aligned.m16n8k16.row.col.f32.bf16.bf16.f32 " \
        "{%0,%1,%2,%3},{%4,%5,%6,%7},{%8,%9},{%0,%1,%2,%3};" \
        : "+f"((d)[0]), "+f"((d)[1]), "+f"((d)[2]), "+f"((d)[3]) \
        : "r"(a0), "r"(a1), "r"(a2), "r"(a3), "r"(b0), "r"(b1))

// ---------------------------------------------------------------------------
// fp32 -> (bf16 hi, bf16 lo) split, 4 elems/thread
// ---------------------------------------------------------------------------
__global__ __launch_bounds__(256) void split_bf16(
    const float4* __restrict__ src, __nv_bfloat162* __restrict__ hi,
    __nv_bfloat162* __restrict__ lo, int n4)
{
    int i = blockIdx.x * 256 + threadIdx.x;
    if (i >= n4) return;
    float4 v = src[i];
    __nv_bfloat16 h0 = __float2bfloat16(v.x), h1 = __float2bfloat16(v.y);
    __nv_bfloat16 h2 = __float2bfloat16(v.z), h3 = __float2bfloat16(v.w);
    __nv_bfloat16 l0 = __float2bfloat16(v.x - __bfloat162float(h0));
    __nv_bfloat16 l1 = __float2bfloat16(v.y - __bfloat162float(h1));
    __nv_bfloat16 l2 = __float2bfloat16(v.z - __bfloat162float(h2));
    __nv_bfloat16 l3 = __float2bfloat16(v.w - __bfloat162float(h3));
    hi[2 * i]     = __halves2bfloat162(h0, h1);
    hi[2 * i + 1] = __halves2bfloat162(h2, h3);
    lo[2 * i]     = __halves2bfloat162(l0, l1);
    lo[2 * i + 1] = __halves2bfloat162(l2, l3);
}

// ---------------------------------------------------------------------------
// HMMA GEMM (NT), 3-term bf16 split, 4-stage cp.async ring.
// BM=BN=128, BK=32, 256 thr (2x4 warps, 64x32/warp).
// blockIdx.z selects the B operand / bias / output (fused QKV or fused IP).
// ---------------------------------------------------------------------------
#define BK      32
#define SSTR    40                    // smem row stride (80B): ldmatrix conflict-free
#define STAGES  4
#define TILE_BYTES  (128 * SSTR * 2)  // 10240
#define STAGE_BYTES (2 * TILE_BYTES)  // A tile + B tile
#define GEMM_SMEM   (STAGES * STAGE_BYTES)

__global__ __launch_bounds__(256) void gemm_mma(
    const __nv_bfloat16* __restrict__ Ah, const __nv_bfloat16* __restrict__ Al,
    const __nv_bfloat16* __restrict__ Bh0, const __nv_bfloat16* __restrict__ Bl0,
    const __nv_bfloat16* __restrict__ Bh1, const __nv_bfloat16* __restrict__ Bl1,
    const __nv_bfloat16* __restrict__ Bh2, const __nv_bfloat16* __restrict__ Bl2,
    const float* __restrict__ bias0, const float* __restrict__ bias1,
    const float* __restrict__ bias2,
    int outBase, int M, int N, int K)
{
    extern __shared__ __align__(16) char smem[];

    const int z = blockIdx.z;
    const __nv_bfloat16* Bh = (z == 0) ? Bh0 : (z == 1) ? Bh1 : Bh2;
    const __nv_bfloat16* Bl = (z == 0) ? Bl0 : (z == 1) ? Bl1 : Bl2;
    const float* bias = (z == 0) ? bias0 : (z == 1) ? bias1 : bias2;
    const int outSel = outBase + z;
    float* C = (outSel == 0) ? g_Q : (outSel == 1) ? g_K :
               (outSel == 2) ? g_V : (outSel == 3) ? g_IPK : g_IPV;

    const int tid = threadIdx.x;
    const int wid = tid >> 5;
    const int lane = tid & 31;
    const int warp_m = wid >> 2;       // 0..1
    const int warp_n = wid & 3;        // 0..3
    const int m0 = blockIdx.y * 128;
    const int n0 = blockIdx.x * 128;

    // per-thread copy coords: one row, one 32B segment (2x16B)
    const int cprow = tid >> 1;
    const int cpg   = (tid & 1) * 2;

    const uint32_t sbase = smem_u32(smem);
    const uint32_t cp_off = (uint32_t)(cprow * SSTR + cpg * 8) * 2;

    // ldmatrix lane-dependent coords
    const int a_row = lane & 15;
    const int a_k   = (lane >> 4) * 8;
    const int b_row = ((lane >> 4) & 1) * 8 + (lane & 7);
    const int b_k   = ((lane >> 3) & 1) * 8;

    float acc[4][4][4];
#pragma unroll
    for (int i = 0; i < 4; i++)
#pragma unroll
        for (int j = 0; j < 4; j++)
#pragma unroll
            for (int e = 0; e < 4; e++) acc[i][j][e] = 0.f;

    const int nkc = K / BK;
    const int NC = 3 * nkc;

    // chunk loader: term 0 = Ah.Bh, 1 = Al.Bh, 2 = Ah.Bl
    auto load_chunk = [&](int c) {
        int t = c / nkc;
        int kc = c - t * nkc;
        const __nv_bfloat16* A = (t == 1) ? Al : Ah;
        const __nv_bfloat16* B = (t == 2) ? Bl : Bh;
        const __nv_bfloat16* Ap = A + (size_t)(m0 + cprow) * K + kc * BK + cpg * 8;
        const __nv_bfloat16* Bp = B + (size_t)(n0 + cprow) * K + kc * BK + cpg * 8;
        uint32_t st = sbase + (uint32_t)(c & (STAGES - 1)) * STAGE_BYTES;
        uint32_t da = st + cp_off;
        uint32_t db = da + TILE_BYTES;
        CP_ASYNC_CG(da, Ap);
        CP_ASYNC_CG(da + 16, Ap + 8);
        CP_ASYNC_CG(db, Bp);
        CP_ASYNC_CG(db + 16, Bp + 8);
    };

    // prologue: fill 3 stages (NC >= 3 always here)
#pragma unroll
    for (int c = 0; c < STAGES - 1; c++) {
        load_chunk(c);
        CP_COMMIT();
    }

    for (int c = 0; c < NC; c++) {
        CP_WAIT2();            // oldest group (chunk c) complete
        __syncthreads();

        const uint32_t st = sbase + (uint32_t)(c & (STAGES - 1)) * STAGE_BYTES;
        const uint32_t aS = st;
        const uint32_t bS = st + TILE_BYTES;

#pragma unroll
        for (int ks = 0; ks < 2; ks++) {
            uint32_t afr[4][4];
#pragma unroll
            for (int ma = 0; ma < 4; ma++) {
                uint32_t addr = aS + (uint32_t)((warp_m * 64 + ma * 16 + a_row) * SSTR
                                                + ks * 16 + a_k) * 2;
                LDMATRIX_X4(afr[ma][0], afr[ma][1], afr[ma][2], afr[ma][3], addr);
            }
            uint32_t bfr[4][2];
#pragma unroll
            for (int np = 0; np < 2; np++) {
                uint32_t addr = bS + (uint32_t)((warp_n * 32 + np * 16 + b_row) * SSTR
                                                + ks * 16 + b_k) * 2;
                uint32_t r0, r1, r2, r3;
                LDMATRIX_X4(r0, r1, r2, r3, addr);
                bfr[np * 2][0] = r0;     bfr[np * 2][1] = r1;
                bfr[np * 2 + 1][0] = r2; bfr[np * 2 + 1][1] = r3;
            }
#pragma unroll
            for (int ma = 0; ma < 4; ma++)
#pragma unroll
                for (int nb = 0; nb < 4; nb++)
                    MMA16816(acc[ma][nb], afr[ma][0], afr[ma][1], afr[ma][2], afr[ma][3],
                             bfr[nb][0], bfr[nb][1]);
        }

        // issue chunk c+3 into the stage just consumed at iteration c-1;
        // empty commit keeps the group-count invariant at the tail.
        if (c + STAGES - 1 < NC) load_chunk(c + STAGES - 1);
        CP_COMMIT();
    }

    // epilogue
    const int er = m0 + warp_m * 64 + (lane >> 2);
    const int ec = n0 + warp_n * 32 + (lane & 3) * 2;
#pragma unroll
    for (int ma = 0; ma < 4; ma++) {
        int row = er + ma * 16;
#pragma unroll
        for (int nb = 0; nb < 4; nb++) {
            int col = ec + nb * 8;
            float b0 = bias ? bias[col] : 0.f;
            float b1 = bias ? bias[col + 1] : 0.f;
            C[(size_t)row * N + col]           = acc[ma][nb][0] + b0;
            C[(size_t)row * N + col + 1]       = acc[ma][nb][1] + b1;
            C[(size_t)(row + 8) * N + col]     = acc[ma][nb][2] + b0;
            C[(size_t)(row + 8) * N + col + 1] = acc[ma][nb][3] + b1;
        }
    }
}

// ---------------------------------------------------------------------------
// RMSNorm + interleaved RoPE on g_Q / g_K
// ---------------------------------------------------------------------------
__global__ __launch_bounds__(256) void rms_rope(
    const float* __restrict__ cosp, const float* __restrict__ sinp,
    const float* __restrict__ qw, const float* __restrict__ kw)
{
    const int warp = threadIdx.x >> 5;
    const int lane = threadIdx.x & 31;
    const int row = blockIdx.x * 8 + warp;
    float* X = (blockIdx.y == 0) ? g_Q : g_K;
    const float* w = (blockIdx.y == 0) ? qw : kw;
    const int s = row / NH;
    const size_t base = (size_t)row * HD + lane * 4;

    float4 x = *(const float4*)(X + base);
    float ss = x.x * x.x + x.y * x.y + x.z * x.z + x.w * x.w;
#pragma unroll
    for (int o = 16; o; o >>= 1) ss += __shfl_xor_sync(0xffffffffu, ss, o);
    float inv = rsqrtf(ss * (1.f / HD) + 1e-6f);

    float4 wv = *(const float4*)(w + lane * 4);
    float y0 = x.x * inv * wv.x, y1 = x.y * inv * wv.y;
    float y2 = x.z * inv * wv.z, y3 = x.w * inv * wv.w;

    float4 c  = *(const float4*)(cosp + (size_t)s * HD + lane * 4);
    float4 sn = *(const float4*)(sinp + (size_t)s * HD + lane * 4);
    float4 o;
    o.x = y0 * c.x - y1 * sn.x;
    o.y = y1 * c.y + y0 * sn.y;
    o.z = y2 * c.z - y3 * sn.z;
    o.w = y3 * c.w + y2 * sn.w;
    *(float4*)(X + base) = o;
}

__global__ __launch_bounds__(256) void ip_rms()
{
    const int warp = threadIdx.x >> 5;
    const int lane = threadIdx.x & 31;
    const int row = blockIdx.x * 8 + warp;
    float* X = (blockIdx.y == 0) ? g_IPK : g_IPV;
    const size_t base = (size_t)row * HD + lane * 4;

    float4 x = *(const float4*)(X + base);
    float ss = x.x * x.x + x.y * x.y + x.z * x.z + x.w * x.w;
#pragma unroll
    for (int o = 16; o; o >>= 1) ss += __shfl_xor_sync(0xffffffffu, ss, o);
    float inv = rsqrtf(ss * (1.f / HD) + 1e-5f);
    x.x *= inv; x.y *= inv; x.z *= inv; x.w *= inv;
    *(float4*)(X + base) = x;
}

// ---------------------------------------------------------------------------
// Fused fp32 flash attention (unchanged — passed at rel_err 2e-6)
// ---------------------------------------------------------------------------
__global__ __launch_bounds__(128) void attn_kernel(float* __restrict__ out)
{
    __shared__ float qs[32][132];
    __shared__ float kv[32][132];
    __shared__ float sc[32][36];
    __shared__ float abuf[32];
    __shared__ float lbuf[32];

    const int tid = threadIdx.x;
    const int h = blockIdx.y;
    const int q0 = blockIdx.x * 32;
    const float scale = 0.08838834764831845f;

#pragma unroll
    for (int it = 0; it < 8; it++) {
        int idx = it * 128 + tid;
        int r = idx >> 5, c4 = idx & 31;
        float4 v = *(const float4*)(g_Q + (size_t)(q0 + r) * HID + h * HD + c4 * 4);
        v.x *= scale; v.y *= scale; v.z *= scale; v.w *= scale;
        *(float4*)&qs[r][c4 * 4] = v;
    }

    float oacc[32];
#pragma unroll
    for (int i = 0; i < 32; i++) oacc[i] = 0.f;
    float mreg = -1e30f, lreg = 0.f;

    const int jg = tid & 3;
    const int ir = tid >> 2;
    const int c = tid;
    __syncthreads();

    for (int phase = 0; phase < 2; phase++) {
        const float* Ksrc = phase ? g_IPK : g_K;
        const float* Vsrc = phase ? g_IPV : g_V;
        const int ntiles = phase ? (IPT / 32) : (SEQ / 32);

        for (int t = 0; t < ntiles; t++) {
            const int k0 = t * 32;
#pragma unroll
            for (int it = 0; it < 8; it++) {
                int idx = it * 128 + tid;
                int r = idx >> 5, c4 = idx & 31;
                *(float4*)&kv[r][c4 * 4] =
                    *(const float4*)(Ksrc + (size_t)(k0 + r) * HID + h * HD + c4 * 4);
            }
            __syncthreads();

            float a8[8];
#pragma unroll
            for (int jj = 0; jj < 8; jj++) a8[jj] = 0.f;
            for (int d4 = 0; d4 < HD; d4 += 4) {
                float4 q4 = *(const float4*)&qs[ir][d4];
#pragma unroll
                for (int jj = 0; jj < 8; jj++) {
                    float4 k4 = *(const float4*)&kv[jg * 8 + jj][d4];
                    a8[jj] += q4.x * k4.x + q4.y * k4.y + q4.z * k4.z + q4.w * k4.w;
                }
            }
#pragma unroll
            for (int jj = 0; jj < 8; jj++) sc[ir][jg * 8 + jj] = a8[jj];
            __syncthreads();

            if (tid < 32) {
                float tm = -1e30f;
#pragma unroll
                for (int j = 0; j < 32; j++) tm = fmaxf(tm, sc[tid][j]);
                float mnew = fmaxf(mreg, tm);
                float alpha = __expf(mreg - mnew);
                float ls = 0.f;
#pragma unroll
                for (int j = 0; j < 32; j++) {
                    float p = __expf(sc[tid][j] - mnew);
                    sc[tid][j] = p;
                    ls += p;
                }
                lreg = lreg * alpha + ls;
                mreg = mnew;
                abuf[tid] = alpha;
            }
            __syncthreads();

#pragma unroll
            for (int it = 0; it < 8; it++) {
                int idx = it * 128 + tid;
                int r = idx >> 5, c4 = idx & 31;
                *(float4*)&kv[r][c4 * 4] =
                    *(const float4*)(Vsrc + (size_t)(k0 + r) * HID + h * HD + c4 * 4);
            }
            __syncthreads();

#pragma unroll
            for (int i = 0; i < 32; i++) oacc[i] *= abuf[i];
#pragma unroll
            for (int j4 = 0; j4 < 8; j4++) {
                float v0 = kv[j4 * 4 + 0][c];
                float v1 = kv[j4 * 4 + 1][c];
                float v2 = kv[j4 * 4 + 2][c];
                float v3 = kv[j4 * 4 + 3][c];
#pragma unroll
                for (int i = 0; i < 32; i++) {
                    float4 p4 = *(const float4*)&sc[i][j4 * 4];
                    oacc[i] += p4.x * v0 + p4.y * v1 + p4.z * v2 + p4.w * v3;
                }
            }
            __syncthreads();
        }

        if (tid < 32) lbuf[tid] = lreg;
        __syncthreads();
        if (phase == 0) {
#pragma unroll
            for (int i = 0; i < 32; i++)
                out[(size_t)(q0 + i) * HID + h * HD + c] = oacc[i] / lbuf[i];
#pragma unroll
            for (int i = 0; i < 32; i++) oacc[i] = 0.f;
            mreg = -1e30f; lreg = 0.f;
        } else {
#pragma unroll
            for (int i = 0; i < 32; i++)
                out[(size_t)(q0 + i) * HID + h * HD + c] += oacc[i] / lbuf[i];
        }
        __syncthreads();
    }
}

// ---------------------------------------------------------------------------
extern "C" void kernel_launch(void* const* d_in, const int* in_sizes, int n_in,
                              void* d_out, int out_size)
{
    const float* hidden = (const float*)d_in[0];
    const float* cosp   = (const float*)d_in[1];
    const float* sinp   = (const float*)d_in[2];
    const float* iph    = (const float*)d_in[3];
    const float* Wq     = (const float*)d_in[4];
    const float* bq     = (const float*)d_in[5];
    const float* Wk     = (const float*)d_in[6];
    const float* bk     = (const float*)d_in[7];
    const float* Wv     = (const float*)d_in[8];
    const float* bv     = (const float*)d_in[9];
    const float* nqw    = (const float*)d_in[10];
    const float* nkw    = (const float*)d_in[11];
    const float* Wkip   = (const float*)d_in[12];
    const float* Wvip   = (const float*)d_in[13];
    float* out = (float*)d_out;

    cudaFuncSetAttribute(gemm_mma, cudaFuncAttributeMaxDynamicSharedMemorySize, GEMM_SMEM);

    __nv_bfloat16 *Hh, *Hl, *Wqh, *Wql, *Wkh, *Wkl, *Wvh, *Wvl;
    __nv_bfloat16 *IPHh, *IPHl, *WKiph, *WKipl, *WViph, *WVipl;
    cudaGetSymbolAddress((void**)&Hh, g_Hh);     cudaGetSymbolAddress((void**)&Hl, g_Hl);
    cudaGetSymbolAddress((void**)&Wqh, g_Wqh);   cudaGetSymbolAddress((void**)&Wql, g_Wql);
    cudaGetSymbolAddress((void**)&Wkh, g_Wkh);   cudaGetSymbolAddress((void**)&Wkl, g_Wkl);
    cudaGetSymbolAddress((void**)&Wvh, g_Wvh);   cudaGetSymbolAddress((void**)&Wvl, g_Wvl);
    cudaGetSymbolAddress((void**)&IPHh, g_IPHh); cudaGetSymbolAddress((void**)&IPHl, g_IPHl);
    cudaGetSymbolAddress((void**)&WKiph, g_WKiph); cudaGetSymbolAddress((void**)&WKipl, g_WKipl);
    cudaGetSymbolAddress((void**)&WViph, g_WViph); cudaGetSymbolAddress((void**)&WVipl, g_WVipl);

    auto split = [](const float* s, __nv_bfloat16* h, __nv_bfloat16* l, int n) {
        int n4 = n / 4;
        split_bf16<<<(n4 + 255) / 256, 256>>>((const float4*)s,
            (__nv_bfloat162*)h, (__nv_bfloat162*)l, n4);
    };
    split(hidden, Hh, Hl, SEQ * HID);
    split(Wq, Wqh, Wql, HID * HID);
    split(Wk, Wkh, Wkl, HID * HID);
    split(Wv, Wvh, Wvl, HID * HID);
    split(iph, IPHh, IPHl, IPT * CAD);
    split(Wkip, WKiph, WKipl, HID * CAD);
    split(Wvip, WViph, WVipl, HID * CAD);

    // fused QKV projections: z = 0,1,2 -> Q,K,V
    dim3 gMain(HID / 128, SEQ / 128, 3);
    gemm_mma<<<gMain, 256, GEMM_SMEM>>>(Hh, Hl,
        Wqh, Wql, Wkh, Wkl, Wvh, Wvl, bq, bk, bv, 0, SEQ, HID, HID);

    // fused IP projections: z = 0,1 -> IPK,IPV
    dim3 gIp(HID / 128, IPT / 128, 2);
    gemm_mma<<<gIp, 256, GEMM_SMEM>>>(IPHh, IPHl,
        WKiph, WKipl, WViph, WVipl, WKiph, WKipl,
        nullptr, nullptr, nullptr, 3, IPT, HID, CAD);

    rms_rope<<<dim3(SEQ * NH / 8, 2), 256>>>(cosp, sinp, nqw, nkw);
    ip_rms<<<dim3(IPT * NH / 8, 2), 256>>>();

    attn_kernel<<<dim3(SEQ / 32, NH), 128>>>(out);
}

// round 7
// speedup vs baseline: 1.3019x; 1.0273x over previous
#include <cuda_runtime.h>
#include <cuda_bf16.h>
#include <cstdint>

#define SEQ  2048
#define HID  3072
#define NH   24
#define HD   128
#define CAD  4096
#define IPT  128

// ---------------- scratch (static __device__ — no allocation allowed) ------
__device__ float g_Q[SEQ * HID];
__device__ float g_K[SEQ * HID];
__device__ float g_V[SEQ * HID];
__device__ float g_IPK[IPT * HID];
__device__ float g_IPV[IPT * HID];

// bf16 hi/lo splits of all GEMM operands
__device__ __nv_bfloat16 g_Hh[SEQ * HID],  g_Hl[SEQ * HID];
__device__ __nv_bfloat16 g_Wqh[HID * HID], g_Wql[HID * HID];
__device__ __nv_bfloat16 g_Wkh[HID * HID], g_Wkl[HID * HID];
__device__ __nv_bfloat16 g_Wvh[HID * HID], g_Wvl[HID * HID];
__device__ __nv_bfloat16 g_IPHh[IPT * CAD], g_IPHl[IPT * CAD];
__device__ __nv_bfloat16 g_WKiph[HID * CAD], g_WKipl[HID * CAD];
__device__ __nv_bfloat16 g_WViph[HID * CAD], g_WVipl[HID * CAD];

// ---------------- asm helpers (all plain-sm_103-legal) ----------------------
__device__ __forceinline__ uint32_t smem_u32(const void* p) {
    uint32_t a;
    asm("{ .reg .u64 t; cvta.to.shared.u64 t, %1; cvt.u32.u64 %0, t; }"
        : "=r"(a) : "l"(p));
    return a;
}

#define CP_ASYNC_CG(sm, gm) \
    asm volatile("cp.async.cg.shared.global [%0], [%1], 16;" :: "r"(sm), "l"(gm))
#define CP_COMMIT() asm volatile("cp.async.commit_group;" ::: "memory")
#define CP_WAIT1()  asm volatile("cp.async.wait_group 1;" ::: "memory")

#define LDMATRIX_X4(r0, r1, r2, r3, addr) \
    asm volatile("ldmatrix.sync.aligned.m8n8.x4.shared.b16 {%0,%1,%2,%3}, [%4];" \
        : "=r"(r0), "=r"(r1), "=r"(r2), "=r"(r3) : "r"(addr))

#define MMA16816(d, a0, a1, a2, a3, b0, b1) \
    asm volatile("mma.sync.aligned.m16n8k16.row.col.f32.bf16.bf16.f32 " \
        "{%0,%1,%2,%3},{%4,%5,%6,%7},{%8,%9},{%0,%1,%2,%3};" \
        : "+f"((d)[0]), "+f"((d)[1]), "+f"((d)[2]), "+f"((d)[3]) \
        : "r"(a0), "r"(a1), "r"(a2), "r"(a3), "r"(b0), "r"(b1))

// ---------------------------------------------------------------------------
// Fused fp32 -> (bf16 hi, bf16 lo) split: up to 4 tensors per launch.
// ---------------------------------------------------------------------------
__global__ __launch_bounds__(256) void split4(
    const float4* __restrict__ s0, const float4* __restrict__ s1,
    const float4* __restrict__ s2, const float4* __restrict__ s3,
    __nv_bfloat162* h0, __nv_bfloat162* h1, __nv_bfloat162* h2, __nv_bfloat162* h3,
    __nv_bfloat162* l0, __nv_bfloat162* l1, __nv_bfloat162* l2, __nv_bfloat162* l3,
    int n0, int n1, int n2, int n3)
{
    const int t = blockIdx.y;
    const float4* s = (t == 0) ? s0 : (t == 1) ? s1 : (t == 2) ? s2 : s3;
    __nv_bfloat162* hi = (t == 0) ? h0 : (t == 1) ? h1 : (t == 2) ? h2 : h3;
    __nv_bfloat162* lo = (t == 0) ? l0 : (t == 1) ? l1 : (t == 2) ? l2 : l3;
    const int n4 = (t == 0) ? n0 : (t == 1) ? n1 : (t == 2) ? n2 : n3;
    if (!s) return;
    int i = blockIdx.x * 256 + threadIdx.x;
    if (i >= n4) return;
    float4 v = s[i];
    __nv_bfloat16 a0 = __float2bfloat16(v.x), a1 = __float2bfloat16(v.y);
    __nv_bfloat16 a2 = __float2bfloat16(v.z), a3 = __float2bfloat16(v.w);
    __nv_bfloat16 b0 = __float2bfloat16(v.x - __bfloat162float(a0));
    __nv_bfloat16 b1 = __float2bfloat16(v.y - __bfloat162float(a1));
    __nv_bfloat16 b2 = __float2bfloat16(v.z - __bfloat162float(a2));
    __nv_bfloat16 b3 = __float2bfloat16(v.w - __bfloat162float(a3));
    hi[2 * i]     = __halves2bfloat162(a0, a1);
    hi[2 * i + 1] = __halves2bfloat162(a2, a3);
    lo[2 * i]     = __halves2bfloat162(b0, b1);
    lo[2 * i + 1] = __halves2bfloat162(b2, b3);
}

// ---------------------------------------------------------------------------
// HMMA GEMM (NT), 3-term bf16 split, 4-tile stages (Ah,Al,Bh,Bl loaded once
// per K-chunk, 3 MMA passes over them). BM=BN=128, BK=32, 256 thr.
// 2-stage cp.async ring, 40KB/stage. blockIdx.z selects B operand / output.
// ---------------------------------------------------------------------------
#define BK      32
#define SSTR    40                       // 80B smem row stride, ldmatrix conflict-free
#define TILE_BYTES  (128 * SSTR * 2)     // 10240
#define STAGE_BYTES (4 * TILE_BYTES)     // Ah, Al, Bh, Bl
#define STAGES  2
#define GEMM_SMEM   (STAGES * STAGE_BYTES)   // 81920

__global__ __launch_bounds__(256, 2) void gemm_mma(
    const __nv_bfloat16* __restrict__ Ah, const __nv_bfloat16* __restrict__ Al,
    const __nv_bfloat16* __restrict__ Bh0, const __nv_bfloat16* __restrict__ Bl0,
    const __nv_bfloat16* __restrict__ Bh1, const __nv_bfloat16* __restrict__ Bl1,
    const __nv_bfloat16* __restrict__ Bh2, const __nv_bfloat16* __restrict__ Bl2,
    const float* __restrict__ bias0, const float* __restrict__ bias1,
    const float* __restrict__ bias2,
    int outBase, int M, int N, int K)
{
    extern __shared__ __align__(16) char smem[];

    const int z = blockIdx.z;
    const __nv_bfloat16* Bh = (z == 0) ? Bh0 : (z == 1) ? Bh1 : Bh2;
    const __nv_bfloat16* Bl = (z == 0) ? Bl0 : (z == 1) ? Bl1 : Bl2;
    const float* bias = (z == 0) ? bias0 : (z == 1) ? bias1 : bias2;
    const int outSel = outBase + z;
    float* C = (outSel == 0) ? g_Q : (outSel == 1) ? g_K :
               (outSel == 2) ? g_V : (outSel == 3) ? g_IPK : g_IPV;

    const int tid = threadIdx.x;
    const int wid = tid >> 5;
    const int lane = tid & 31;
    const int warp_m = wid >> 2;       // 0..1
    const int warp_n = wid & 3;        // 0..3
    const int m0 = blockIdx.y * 128;
    const int n0 = blockIdx.x * 128;

    // per-thread copy coords: one row, one 32B segment (2x16B) per tile
    const int cprow = tid >> 1;
    const int cpg   = (tid & 1) * 2;

    const uint32_t sbase = smem_u32(smem);
    const uint32_t cp_off = (uint32_t)(cprow * SSTR + cpg * 8) * 2;

    // ldmatrix lane-dependent coords
    const int a_row = lane & 15;
    const int a_k   = (lane >> 4) * 8;
    const int b_row = ((lane >> 4) & 1) * 8 + (lane & 7);
    const int b_k   = ((lane >> 3) & 1) * 8;

    float acc[4][4][4];
#pragma unroll
    for (int i = 0; i < 4; i++)
#pragma unroll
        for (int j = 0; j < 4; j++)
#pragma unroll
            for (int e = 0; e < 4; e++) acc[i][j][e] = 0.f;

    const int nkc = K / BK;

    // load one K-chunk: all 4 tiles (Ah, Al, Bh, Bl)
    auto load_chunk = [&](int c) {
        uint32_t st = sbase + (uint32_t)(c & 1) * STAGE_BYTES;
        const __nv_bfloat16* srcs[4] = { Ah, Al, Bh, Bl };
#pragma unroll
        for (int t = 0; t < 4; t++) {
            const int rowbase = (t < 2) ? m0 : n0;
            const __nv_bfloat16* gp = srcs[t] + (size_t)(rowbase + cprow) * K
                                      + c * BK + cpg * 8;
            uint32_t d = st + (uint32_t)t * TILE_BYTES + cp_off;
            CP_ASYNC_CG(d, gp);
            CP_ASYNC_CG(d + 16, gp + 8);
        }
    };

    // prologue: 2 stages
    load_chunk(0); CP_COMMIT();
    if (nkc > 1) load_chunk(1);
    CP_COMMIT();

    for (int c = 0; c < nkc; c++) {
        CP_WAIT1();
        __syncthreads();

        const uint32_t st = sbase + (uint32_t)(c & 1) * STAGE_BYTES;

#pragma unroll
        for (int ks = 0; ks < 2; ks++) {
            uint32_t afr[4][4];
            // Ah fragments
#pragma unroll
            for (int ma = 0; ma < 4; ma++) {
                uint32_t addr = st + (uint32_t)((warp_m * 64 + ma * 16 + a_row) * SSTR
                                                + ks * 16 + a_k) * 2;
                LDMATRIX_X4(afr[ma][0], afr[ma][1], afr[ma][2], afr[ma][3], addr);
            }
            // Bh and Bl fragments
            uint32_t bh[4][2], bl[4][2];
#pragma unroll
            for (int np = 0; np < 2; np++) {
                uint32_t ab = st + 2 * TILE_BYTES
                    + (uint32_t)((warp_n * 32 + np * 16 + b_row) * SSTR + ks * 16 + b_k) * 2;
                uint32_t r0, r1, r2, r3;
                LDMATRIX_X4(r0, r1, r2, r3, ab);
                bh[np * 2][0] = r0;     bh[np * 2][1] = r1;
                bh[np * 2 + 1][0] = r2; bh[np * 2 + 1][1] = r3;
                uint32_t lb = ab + TILE_BYTES;
                LDMATRIX_X4(r0, r1, r2, r3, lb);
                bl[np * 2][0] = r0;     bl[np * 2][1] = r1;
                bl[np * 2 + 1][0] = r2; bl[np * 2 + 1][1] = r3;
            }
            // Ah*Bh + Ah*Bl
#pragma unroll
            for (int ma = 0; ma < 4; ma++)
#pragma unroll
                for (int nb = 0; nb < 4; nb++) {
                    MMA16816(acc[ma][nb], afr[ma][0], afr[ma][1], afr[ma][2], afr[ma][3],
                             bh[nb][0], bh[nb][1]);
                    MMA16816(acc[ma][nb], afr[ma][0], afr[ma][1], afr[ma][2], afr[ma][3],
                             bl[nb][0], bl[nb][1]);
                }
            // Al fragments (overwrite afr), Al*Bh
#pragma unroll
            for (int ma = 0; ma < 4; ma++) {
                uint32_t addr = st + TILE_BYTES
                    + (uint32_t)((warp_m * 64 + ma * 16 + a_row) * SSTR + ks * 16 + a_k) * 2;
                LDMATRIX_X4(afr[ma][0], afr[ma][1], afr[ma][2], afr[ma][3], addr);
            }
#pragma unroll
            for (int ma = 0; ma < 4; ma++)
#pragma unroll
                for (int nb = 0; nb < 4; nb++)
                    MMA16816(acc[ma][nb], afr[ma][0], afr[ma][1], afr[ma][2], afr[ma][3],
                             bh[nb][0], bh[nb][1]);
        }

        __syncthreads();          // all warps done reading stage c&1
        if (c + 2 < nkc) load_chunk(c + 2);
        CP_COMMIT();              // empty commit at tail keeps group count invariant
    }

    // epilogue
    const int er = m0 + warp_m * 64 + (lane >> 2);
    const int ec = n0 + warp_n * 32 + (lane & 3) * 2;
#pragma unroll
    for (int ma = 0; ma < 4; ma++) {
        int row = er + ma * 16;
#pragma unroll
        for (int nb = 0; nb < 4; nb++) {
            int col = ec + nb * 8;
            float b0 = bias ? bias[col] : 0.f;
            float b1 = bias ? bias[col + 1] : 0.f;
            C[(size_t)row * N + col]           = acc[ma][nb][0] + b0;
            C[(size_t)row * N + col + 1]       = acc[ma][nb][1] + b1;
            C[(size_t)(row + 8) * N + col]     = acc[ma][nb][2] + b0;
            C[(size_t)(row + 8) * N + col + 1] = acc[ma][nb][3] + b1;
        }
    }
}

// ---------------------------------------------------------------------------
// RMSNorm + interleaved RoPE on g_Q / g_K
// ---------------------------------------------------------------------------
__global__ __launch_bounds__(256) void rms_rope(
    const float* __restrict__ cosp, const float* __restrict__ sinp,
    const float* __restrict__ qw, const float* __restrict__ kw)
{
    const int warp = threadIdx.x >> 5;
    const int lane = threadIdx.x & 31;
    const int row = blockIdx.x * 8 + warp;
    float* X = (blockIdx.y == 0) ? g_Q : g_K;
    const float* w = (blockIdx.y == 0) ? qw : kw;
    const int s = row / NH;
    const size_t base = (size_t)row * HD + lane * 4;

    float4 x = *(const float4*)(X + base);
    float ss = x.x * x.x + x.y * x.y + x.z * x.z + x.w * x.w;
#pragma unroll
    for (int o = 16; o; o >>= 1) ss += __shfl_xor_sync(0xffffffffu, ss, o);
    float inv = rsqrtf(ss * (1.f / HD) + 1e-6f);

    float4 wv = *(const float4*)(w + lane * 4);
    float y0 = x.x * inv * wv.x, y1 = x.y * inv * wv.y;
    float y2 = x.z * inv * wv.z, y3 = x.w * inv * wv.w;

    float4 c  = *(const float4*)(cosp + (size_t)s * HD + lane * 4);
    float4 sn = *(const float4*)(sinp + (size_t)s * HD + lane * 4);
    float4 o;
    o.x = y0 * c.x - y1 * sn.x;
    o.y = y1 * c.y + y0 * sn.y;
    o.z = y2 * c.z - y3 * sn.z;
    o.w = y3 * c.w + y2 * sn.w;
    *(float4*)(X + base) = o;
}

__global__ __launch_bounds__(256) void ip_rms()
{
    const int warp = threadIdx.x >> 5;
    const int lane = threadIdx.x & 31;
    const int row = blockIdx.x * 8 + warp;
    float* X = (blockIdx.y == 0) ? g_IPK : g_IPV;
    const size_t base = (size_t)row * HD + lane * 4;

    float4 x = *(const float4*)(X + base);
    float ss = x.x * x.x + x.y * x.y + x.z * x.z + x.w * x.w;
#pragma unroll
    for (int o = 16; o; o >>= 1) ss += __shfl_xor_sync(0xffffffffu, ss, o);
    float inv = rsqrtf(ss * (1.f / HD) + 1e-5f);
    x.x *= inv; x.y *= inv; x.z *= inv; x.w *= inv;
    *(float4*)(X + base) = x;
}

// ---------------------------------------------------------------------------
// Fused fp32 flash attention (unchanged — rel_err 2e-6 standalone)
// ---------------------------------------------------------------------------
__global__ __launch_bounds__(128) void attn_kernel(float* __restrict__ out)
{
    __shared__ float qs[32][132];
    __shared__ float kv[32][132];
    __shared__ float sc[32][36];
    __shared__ float abuf[32];
    __shared__ float lbuf[32];

    const int tid = threadIdx.x;
    const int h = blockIdx.y;
    const int q0 = blockIdx.x * 32;
    const float scale = 0.08838834764831845f;

#pragma unroll
    for (int it = 0; it < 8; it++) {
        int idx = it * 128 + tid;
        int r = idx >> 5, c4 = idx & 31;
        float4 v = *(const float4*)(g_Q + (size_t)(q0 + r) * HID + h * HD + c4 * 4);
        v.x *= scale; v.y *= scale; v.z *= scale; v.w *= scale;
        *(float4*)&qs[r][c4 * 4] = v;
    }

    float oacc[32];
#pragma unroll
    for (int i = 0; i < 32; i++) oacc[i] = 0.f;
    float mreg = -1e30f, lreg = 0.f;

    const int jg = tid & 3;
    const int ir = tid >> 2;
    const int c = tid;
    __syncthreads();

    for (int phase = 0; phase < 2; phase++) {
        const float* Ksrc = phase ? g_IPK : g_K;
        const float* Vsrc = phase ? g_IPV : g_V;
        const int ntiles = phase ? (IPT / 32) : (SEQ / 32);

        for (int t = 0; t < ntiles; t++) {
            const int k0 = t * 32;
#pragma unroll
            for (int it = 0; it < 8; it++) {
                int idx = it * 128 + tid;
                int r = idx >> 5, c4 = idx & 31;
                *(float4*)&kv[r][c4 * 4] =
                    *(const float4*)(Ksrc + (size_t)(k0 + r) * HID + h * HD + c4 * 4);
            }
            __syncthreads();

            float a8[8];
#pragma unroll
            for (int jj = 0; jj < 8; jj++) a8[jj] = 0.f;
            for (int d4 = 0; d4 < HD; d4 += 4) {
                float4 q4 = *(const float4*)&qs[ir][d4];
#pragma unroll
                for (int jj = 0; jj < 8; jj++) {
                    float4 k4 = *(const float4*)&kv[jg * 8 + jj][d4];
                    a8[jj] += q4.x * k4.x + q4.y * k4.y + q4.z * k4.z + q4.w * k4.w;
                }
            }
#pragma unroll
            for (int jj = 0; jj < 8; jj++) sc[ir][jg * 8 + jj] = a8[jj];
            __syncthreads();

            if (tid < 32) {
                float tm = -1e30f;
#pragma unroll
                for (int j = 0; j < 32; j++) tm = fmaxf(tm, sc[tid][j]);
                float mnew = fmaxf(mreg, tm);
                float alpha = __expf(mreg - mnew);
                float ls = 0.f;
#pragma unroll
                for (int j = 0; j < 32; j++) {
                    float p = __expf(sc[tid][j] - mnew);
                    sc[tid][j] = p;
                    ls += p;
                }
                lreg = lreg * alpha + ls;
                mreg = mnew;
                abuf[tid] = alpha;
            }
            __syncthreads();

#pragma unroll
            for (int it = 0; it < 8; it++) {
                int idx = it * 128 + tid;
                int r = idx >> 5, c4 = idx & 31;
                *(float4*)&kv[r][c4 * 4] =
                    *(const float4*)(Vsrc + (size_t)(k0 + r) * HID + h * HD + c4 * 4);
            }
            __syncthreads();

#pragma unroll
            for (int i = 0; i < 32; i++) oacc[i] *= abuf[i];
#pragma unroll
            for (int j4 = 0; j4 < 8; j4++) {
                float v0 = kv[j4 * 4 + 0][c];
                float v1 = kv[j4 * 4 + 1][c];
                float v2 = kv[j4 * 4 + 2][c];
                float v3 = kv[j4 * 4 + 3][c];
#pragma unroll
                for (int i = 0; i < 32; i++) {
                    float4 p4 = *(const float4*)&sc[i][j4 * 4];
                    oacc[i] += p4.x * v0 + p4.y * v1 + p4.z * v2 + p4.w * v3;
                }
            }
            __syncthreads();
        }

        if (tid < 32) lbuf[tid] = lreg;
        __syncthreads();
        if (phase == 0) {
#pragma unroll
            for (int i = 0; i < 32; i++)
                out[(size_t)(q0 + i) * HID + h * HD + c] = oacc[i] / lbuf[i];
#pragma unroll
            for (int i = 0; i < 32; i++) oacc[i] = 0.f;
            mreg = -1e30f; lreg = 0.f;
        } else {
#pragma unroll
            for (int i = 0; i < 32; i++)
                out[(size_t)(q0 + i) * HID + h * HD + c] += oacc[i] / lbuf[i];
        }
        __syncthreads();
    }
}

// ---------------------------------------------------------------------------
extern "C" void kernel_launch(void* const* d_in, const int* in_sizes, int n_in,
                              void* d_out, int out_size)
{
    const float* hidden = (const float*)d_in[0];
    const float* cosp   = (const float*)d_in[1];
    const float* sinp   = (const float*)d_in[2];
    const float* iph    = (const float*)d_in[3];
    const float* Wq     = (const float*)d_in[4];
    const float* bq     = (const float*)d_in[5];
    const float* Wk     = (const float*)d_in[6];
    const float* bk     = (const float*)d_in[7];
    const float* Wv     = (const float*)d_in[8];
    const float* bv     = (const float*)d_in[9];
    const float* nqw    = (const float*)d_in[10];
    const float* nkw    = (const float*)d_in[11];
    const float* Wkip   = (const float*)d_in[12];
    const float* Wvip   = (const float*)d_in[13];
    float* out = (float*)d_out;

    cudaFuncSetAttribute(gemm_mma, cudaFuncAttributeMaxDynamicSharedMemorySize, GEMM_SMEM);

    __nv_bfloat16 *Hh, *Hl, *Wqh, *Wql, *Wkh, *Wkl, *Wvh, *Wvl;
    __nv_bfloat16 *IPHh, *IPHl, *WKiph, *WKipl, *WViph, *WVipl;
    cudaGetSymbolAddress((void**)&Hh, g_Hh);     cudaGetSymbolAddress((void**)&Hl, g_Hl);
    cudaGetSymbolAddress((void**)&Wqh, g_Wqh);   cudaGetSymbolAddress((void**)&Wql, g_Wql);
    cudaGetSymbolAddress((void**)&Wkh, g_Wkh);   cudaGetSymbolAddress((void**)&Wkl, g_Wkl);
    cudaGetSymbolAddress((void**)&Wvh, g_Wvh);   cudaGetSymbolAddress((void**)&Wvl, g_Wvl);
    cudaGetSymbolAddress((void**)&IPHh, g_IPHh); cudaGetSymbolAddress((void**)&IPHl, g_IPHl);
    cudaGetSymbolAddress((void**)&WKiph, g_WKiph); cudaGetSymbolAddress((void**)&WKipl, g_WKipl);
    cudaGetSymbolAddress((void**)&WViph, g_WViph); cudaGetSymbolAddress((void**)&WVipl, g_WVipl);

    // n4 element counts (float4 units)
    const int n4_H    = SEQ * HID / 4;       // 1572864
    const int n4_IPH  = IPT * CAD / 4;       // 131072
    const int n4_W    = HID * HID / 4;       // 2359296
    const int n4_Wip  = HID * CAD / 4;       // 3145728

    // Launch 1: split hidden, iph, Wq
    split4<<<dim3((n4_W + 255) / 256, 3), 256>>>(
        (const float4*)hidden, (const float4*)iph, (const float4*)Wq, nullptr,
        (__nv_bfloat162*)Hh, (__nv_bfloat162*)IPHh, (__nv_bfloat162*)Wqh, nullptr,
        (__nv_bfloat162*)Hl, (__nv_bfloat162*)IPHl, (__nv_bfloat162*)Wql, nullptr,
        n4_H, n4_IPH, n4_W, 0);

    // Launch 2: split Wk, Wv, Wkip, Wvip
    split4<<<dim3((n4_Wip + 255) / 256, 4), 256>>>(
        (const float4*)Wk, (const float4*)Wv, (const float4*)Wkip, (const float4*)Wvip,
        (__nv_bfloat162*)Wkh, (__nv_bfloat162*)Wvh, (__nv_bfloat162*)WKiph, (__nv_bfloat162*)WViph,
        (__nv_bfloat162*)Wkl, (__nv_bfloat162*)Wvl, (__nv_bfloat162*)WKipl, (__nv_bfloat162*)WVipl,
        n4_W, n4_W, n4_Wip, n4_Wip);

    // Launch 3: fused IP projections (z = 0,1 -> IPK,IPV)
    dim3 gIp(HID / 128, IPT / 128, 2);
    gemm_mma<<<gIp, 256, GEMM_SMEM>>>(IPHh, IPHl,
        WKiph, WKipl, WViph, WVipl, WKiph, WKipl,
        nullptr, nullptr, nullptr, 3, IPT, HID, CAD);

    // Launch 4: IP rmsnorm
    ip_rms<<<dim3(IPT * NH / 8, 2), 256>>>();

    // Launch 5 (ncu-captured): fused QKV projections (z = 0,1,2 -> Q,K,V)
    dim3 gMain(HID / 128, SEQ / 128, 3);
    gemm_mma<<<gMain, 256, GEMM_SMEM>>>(Hh, Hl,
        Wqh, Wql, Wkh, Wkl, Wvh, Wvl, bq, bk, bv, 0, SEQ, HID, HID);

    // Launch 6: Q/K rmsnorm + rope
    rms_rope<<<dim3(SEQ * NH / 8, 2), 256>>>(cosp, sinp, nqw, nkw);

    // Launch 7: fused attention
    attn_kernel<<<dim3(SEQ / 32, NH), 128>>>(out);
}